// round 1
// baseline (speedup 1.0000x reference)
#include <cuda_runtime.h>
#include <cstdint>

#define BSZ 1024

// ---------------- static device buffers (no allocation allowed) ----------------
__device__ int8_t g_a0[BSZ*32*32*4];          // inquant, NHWC4 (c3 + zero pad)
__device__ int8_t g_c0[BSZ*30*30*64];
__device__ int8_t g_c1[BSZ*28*28*64];
__device__ int8_t g_p1[BSZ*14*14*64];
__device__ int8_t g_c2[BSZ*12*12*128];
__device__ int8_t g_c3[BSZ*10*10*128];
__device__ int8_t g_p3[BSZ*5*5*128];
__device__ int8_t g_c4[BSZ*3*3*256];
__device__ int8_t g_c5[BSZ*256];
__device__ int8_t g_f0[BSZ*512];
__device__ int8_t g_f1[BSZ*512];

__device__ int8_t g_w0[64*9*4];
__device__ int8_t g_w1[64*9*64];
__device__ int8_t g_w2[128*9*64];
__device__ int8_t g_w3[128*9*128];
__device__ int8_t g_w4[256*9*128];
__device__ int8_t g_w5[256*9*256];
__device__ int8_t g_wf0[512*256];
__device__ int8_t g_wf1[512*512];
__device__ int8_t g_wf2[10*512];

__device__ float g_bns[6*256], g_bnm[6*256], g_bnb[6*256];
__device__ float g_fns[2*512], g_fnm[2*512], g_fnb[2*512];

// ---------------- helpers ----------------
__device__ __forceinline__ int8_t qtern(float y){
    float r = rintf(y);                 // half-even, matches jnp.round
    r = fminf(fmaxf(r, -1.f), 1.f);
    return (int8_t)r;
}

// ---------------- prep kernels ----------------
__global__ void k_inquant(const float* __restrict__ x, int8_t* __restrict__ out){
    int idx = blockIdx.x*256 + threadIdx.x;           // over BSZ*1024 pixels
    if (idx >= BSZ*1024) return;
    int b = idx >> 10, p = idx & 1023;
    const float* xb = x + (size_t)b*3072;
    char4 r;
    float v;
    v = rintf(xb[p]        *128.f); v = fminf(fmaxf(v,-128.f),127.f); r.x = (signed char)v;
    v = rintf(xb[1024+p]   *128.f); v = fminf(fmaxf(v,-128.f),127.f); r.y = (signed char)v;
    v = rintf(xb[2048+p]   *128.f); v = fminf(fmaxf(v,-128.f),127.f); r.z = (signed char)v;
    r.w = 0;
    ((char4*)out)[idx] = r;
}

// OIHW float -> [oc][k][CIP] int8 ternary (CIP may pad CI with zeros)
__global__ void k_wprep_conv(const float* __restrict__ src, int8_t* __restrict__ dst,
                             int CI, int CIP, int CO){
    int idx = blockIdx.x*256 + threadIdx.x;
    int tot = CO*9*CIP;
    if (idx >= tot) return;
    int c  = idx % CIP;
    int k  = (idx / CIP) % 9;
    int oc = idx / (9*CIP);
    int8_t q = 0;
    if (c < CI){
        float v = src[(size_t)(oc*CI + c)*9 + k];
        float r = rintf(v);
        r = fminf(fmaxf(r, -1.f), 1.f);
        q = (int8_t)r;
    }
    dst[idx] = q;
}

__global__ void k_wprep_fc(const float* __restrict__ src, int8_t* __restrict__ dst, int n){
    int idx = blockIdx.x*256 + threadIdx.x;
    if (idx >= n) return;
    float r = rintf(src[idx]);
    r = fminf(fmaxf(r, -1.f), 1.f);
    dst[idx] = (int8_t)r;
}

__global__ void k_bnprep(const float* __restrict__ p, int C,
                         float* __restrict__ s, float* __restrict__ m, float* __restrict__ b){
    int c = blockIdx.x*256 + threadIdx.x;
    if (c >= C) return;
    float g  = p[c];
    float bb = p[C + c];
    float mm = p[2*C + c];
    float vv = p[3*C + c];
    s[c] = g / sqrtf(vv + 1e-4f);
    m[c] = mm;
    b[c] = bb;
}

// ---------------- conv kernel ----------------
// NHWC int8 in -> NHWC int8 ternary out, fused BN + aquant.
// SMEM: weight tile [OCT][9][CIN] + input images transposed [img][c16][pixel].
template<int CIN,int COUT,int OCT,int HIN,int WIN,int NIMG,bool FIRST>
__global__ void __launch_bounds__(256) k_conv(
    const int8_t* __restrict__ in, const int8_t* __restrict__ wt,
    const float* __restrict__ bs, const float* __restrict__ bm, const float* __restrict__ bb,
    int8_t* __restrict__ out)
{
    constexpr int HOUT = HIN-2, WOUT = WIN-2;
    constexpr int NPIX = HOUT*WOUT, INPIX = HIN*WIN;
    constexpr int NC   = FIRST ? 1 : CIN/16;     // granules per pixel (16B; FIRST: one 4B)
    constexpr int NOCG = OCT/16;
    constexpr int WB   = OCT*9*CIN;
    extern __shared__ int8_t smem[];
    int8_t* s_w  = smem;
    int8_t* s_in = smem + WB;

    const int tid  = threadIdx.x;
    const int img0 = blockIdx.x * NIMG;
    const int ocb  = blockIdx.y * OCT;

    { // weight tile
        const int4* src = (const int4*)(wt + (size_t)ocb*9*CIN);
        int4* dst = (int4*)s_w;
        #pragma unroll 4
        for (int i = tid; i < WB/16; i += 256) dst[i] = src[i];
    }
    if (FIRST){
        const int* src = (const int*)(in + (size_t)img0*INPIX*4);
        int* dst = (int*)s_in;
        for (int i = tid; i < NIMG*INPIX; i += 256) dst[i] = src[i];
    } else {
        const int4* src = (const int4*)(in + (size_t)img0*INPIX*CIN);
        int4* dst = (int4*)s_in;
        for (int i = tid; i < NIMG*INPIX*NC; i += 256){
            int c  = i % NC;
            int p  = i / NC;
            int im = p / INPIX;
            int pp = p % INPIX;
            dst[(im*NC + c)*INPIX + pp] = src[i];   // transpose: [im][c16][pixel]
        }
    }
    __syncthreads();

    constexpr int TOT = NIMG*NPIX*NOCG;
    for (int t = tid; t < TOT; t += 256){
        int pix = t % NPIX;
        int r2  = t / NPIX;
        int ocg = r2 % NOCG;
        int im  = r2 / NOCG;
        int oy = pix / WOUT, ox = pix % WOUT;
        int acc[16];
        #pragma unroll
        for (int j=0;j<16;j++) acc[j]=0;
        const int8_t* wb_ = s_w + (size_t)ocg*16*9*CIN;

        #pragma unroll 1
        for (int ky=0; ky<3; ky++){
            #pragma unroll
            for (int kx=0; kx<3; kx++){
                const int p  = (oy+ky)*WIN + ox + kx;
                const int kk = ky*3 + kx;
                if (FIRST){
                    const int a = ((const int*)s_in)[im*INPIX + p];
                    #pragma unroll
                    for (int j=0;j<16;j++){
                        int w = *(const int*)(wb_ + (j*9 + kk)*4);
                        acc[j] = __dp4a(a, w, acc[j]);
                    }
                } else {
                    #pragma unroll 2
                    for (int c=0;c<NC;c++){
                        const int4 a = ((const int4*)s_in)[(im*NC + c)*INPIX + p];
                        #pragma unroll
                        for (int j=0;j<16;j++){
                            const int4 w = *(const int4*)(wb_ + (j*9 + kk)*CIN + c*16);
                            acc[j] = __dp4a(a.x, w.x, acc[j]);
                            acc[j] = __dp4a(a.y, w.y, acc[j]);
                            acc[j] = __dp4a(a.z, w.z, acc[j]);
                            acc[j] = __dp4a(a.w, w.w, acc[j]);
                        }
                    }
                }
            }
        }
        union { int8_t b[16]; int4 v; } q;
        #pragma unroll
        for (int j=0;j<16;j++){
            int oc = ocb + ocg*16 + j;
            float v = (float)acc[j];
            if (FIRST) v *= (1.0f/128.0f);
            float y = (v - bm[oc]) * bs[oc] + bb[oc];
            q.b[j] = qtern(y);
        }
        *(int4*)(out + ((size_t)(img0+im)*NPIX + pix)*COUT + ocb + ocg*16) = q.v;
    }
}

// ---------------- pool (avg 2x2 + aquant) ----------------
template<int C,int HIN,int WIN>
__global__ void k_pool(const int8_t* __restrict__ in, int8_t* __restrict__ out){
    constexpr int HO=HIN/2, WO=WIN/2, C4=C/4;
    constexpr int TOT = BSZ*HO*WO*C4;
    int idx = blockIdx.x*256 + threadIdx.x;
    if (idx >= TOT) return;
    int c4 = idx % C4;
    int rr = idx / C4;
    int ox = rr % WO; rr /= WO;
    int oy = rr % HO;
    int b  = rr / HO;
    const int8_t* base = in + ((size_t)(b*HIN + 2*oy)*WIN + 2*ox)*C + c4*4;
    char4 a0 = *(const char4*)base;
    char4 a1 = *(const char4*)(base + C);
    char4 a2 = *(const char4*)(base + (size_t)WIN*C);
    char4 a3 = *(const char4*)(base + (size_t)WIN*C + C);
    char4 o;
    o.x = qtern((float)(a0.x+a1.x+a2.x+a3.x) * 0.25f);
    o.y = qtern((float)(a0.y+a1.y+a2.y+a3.y) * 0.25f);
    o.z = qtern((float)(a0.z+a1.z+a2.z+a3.z) * 0.25f);
    o.w = qtern((float)(a0.w+a1.w+a2.w+a3.w) * 0.25f);
    ((char4*)out)[idx] = o;
}

// ---------------- FC (also conv5 as FI=2304) ----------------
template<int FI,int FO,int BT>
__global__ void __launch_bounds__(256) k_fc(
    const int8_t* __restrict__ in, const int8_t* __restrict__ wt,
    const float* __restrict__ bs, const float* __restrict__ bm, const float* __restrict__ bb,
    int8_t* __restrict__ out)
{
    __shared__ int8_t s_a[BT*FI];
    const int b0 = blockIdx.x*BT, tid = threadIdx.x;
    const int4* src = (const int4*)(in + (size_t)b0*FI);
    for (int i = tid; i < BT*FI/16; i += 256) ((int4*)s_a)[i] = src[i];
    __syncthreads();
    for (int oc = tid; oc < FO; oc += 256){
        int acc[BT];
        #pragma unroll
        for (int j=0;j<BT;j++) acc[j]=0;
        const int4* wr = (const int4*)(wt + (size_t)oc*FI);
        #pragma unroll 4
        for (int c=0;c<FI/16;c++){
            int4 w = wr[c];
            #pragma unroll
            for (int j=0;j<BT;j++){
                int4 a = ((const int4*)s_a)[j*(FI/16)+c];
                acc[j]=__dp4a(a.x,w.x,acc[j]);
                acc[j]=__dp4a(a.y,w.y,acc[j]);
                acc[j]=__dp4a(a.z,w.z,acc[j]);
                acc[j]=__dp4a(a.w,w.w,acc[j]);
            }
        }
        #pragma unroll
        for (int j=0;j<BT;j++){
            float y = ((float)acc[j] - bm[oc]) * bs[oc] + bb[oc];
            out[(size_t)(b0+j)*FO + oc] = qtern(y);
        }
    }
}

__global__ void k_fc_last(const int8_t* __restrict__ in, const int8_t* __restrict__ wt,
                          const float* __restrict__ tn, float* __restrict__ out){
    __shared__ int8_t s_a[512];
    int b = blockIdx.x, tid = threadIdx.x;
    for (int i = tid; i < 32; i += 256)
        ((int4*)s_a)[i] = ((const int4*)(in + (size_t)b*512))[i];
    __syncthreads();
    if (tid < 10){
        const int4* wr = (const int4*)(wt + (size_t)tid*512);
        int acc = 0;
        #pragma unroll 8
        for (int c=0;c<32;c++){
            int4 a = ((const int4*)s_a)[c];
            int4 w = wr[c];
            acc=__dp4a(a.x,w.x,acc); acc=__dp4a(a.y,w.y,acc);
            acc=__dp4a(a.z,w.z,acc); acc=__dp4a(a.w,w.w,acc);
        }
        float y = ((float)acc - tn[2]) / sqrtf(tn[3] + 1e-4f) * tn[0] + tn[1];
        out[b*10 + tid] = y;
    }
}

// ---------------- host ----------------
extern "C" void kernel_launch(void* const* d_in, const int* in_sizes, int n_in,
                              void* d_out, int out_size)
{
    const float *x=0, *wc[6]={0,0,0,0,0,0}, *bnc[6]={0,0,0,0,0,0};
    const float *wf[3]={0,0,0}, *bnf[2]={0,0}, *tn=0;
    int n256=0, n512=0, n1024=0, n2048=0;
    for (int i=0;i<n_in;i++){
        const float* p = (const float*)d_in[i];
        switch (in_sizes[i]){
            case 3145728: x = p; break;
            case 1728:    wc[0]=p; break;
            case 36864:   wc[1]=p; break;
            case 73728:   wc[2]=p; break;
            case 147456:  wc[3]=p; break;
            case 294912:  wc[4]=p; break;
            case 589824:  wc[5]=p; break;
            case 131072:  wf[0]=p; break;
            case 262144:  wf[1]=p; break;
            case 5120:    wf[2]=p; break;
            case 256:     if(n256 <2) bnc[0+n256++ ]=p; break;
            case 512:     if(n512 <2) bnc[2+n512++ ]=p; break;
            case 1024:    if(n1024<2) bnc[4+n1024++]=p; break;
            case 2048:    if(n2048<2) bnf[n2048++  ]=p; break;
            case 4:       tn = p; break;
            default: break;
        }
    }

    int8_t *a0,*c0,*c1,*p1,*c2,*c3,*p3,*c4,*c5,*f0,*f1;
    int8_t *w0,*w1,*w2,*w3,*w4,*w5,*wf0d,*wf1d,*wf2d;
    float *bns,*bnm,*bnb,*fns,*fnm,*fnb;
    cudaGetSymbolAddress((void**)&a0, g_a0);  cudaGetSymbolAddress((void**)&c0, g_c0);
    cudaGetSymbolAddress((void**)&c1, g_c1);  cudaGetSymbolAddress((void**)&p1, g_p1);
    cudaGetSymbolAddress((void**)&c2, g_c2);  cudaGetSymbolAddress((void**)&c3, g_c3);
    cudaGetSymbolAddress((void**)&p3, g_p3);  cudaGetSymbolAddress((void**)&c4, g_c4);
    cudaGetSymbolAddress((void**)&c5, g_c5);  cudaGetSymbolAddress((void**)&f0, g_f0);
    cudaGetSymbolAddress((void**)&f1, g_f1);
    cudaGetSymbolAddress((void**)&w0, g_w0);  cudaGetSymbolAddress((void**)&w1, g_w1);
    cudaGetSymbolAddress((void**)&w2, g_w2);  cudaGetSymbolAddress((void**)&w3, g_w3);
    cudaGetSymbolAddress((void**)&w4, g_w4);  cudaGetSymbolAddress((void**)&w5, g_w5);
    cudaGetSymbolAddress((void**)&wf0d, g_wf0); cudaGetSymbolAddress((void**)&wf1d, g_wf1);
    cudaGetSymbolAddress((void**)&wf2d, g_wf2);
    cudaGetSymbolAddress((void**)&bns, g_bns); cudaGetSymbolAddress((void**)&bnm, g_bnm);
    cudaGetSymbolAddress((void**)&bnb, g_bnb);
    cudaGetSymbolAddress((void**)&fns, g_fns); cudaGetSymbolAddress((void**)&fnm, g_fnm);
    cudaGetSymbolAddress((void**)&fnb, g_fnb);

    const int T = 256;
    // ---- prep
    k_inquant<<<(BSZ*1024+T-1)/T, T>>>(x, a0);
    k_wprep_conv<<<(64*9*4   +T-1)/T, T>>>(wc[0], w0, 3,   4,   64);
    k_wprep_conv<<<(64*9*64  +T-1)/T, T>>>(wc[1], w1, 64,  64,  64);
    k_wprep_conv<<<(128*9*64 +T-1)/T, T>>>(wc[2], w2, 64,  64,  128);
    k_wprep_conv<<<(128*9*128+T-1)/T, T>>>(wc[3], w3, 128, 128, 128);
    k_wprep_conv<<<(256*9*128+T-1)/T, T>>>(wc[4], w4, 128, 128, 256);
    k_wprep_conv<<<(256*9*256+T-1)/T, T>>>(wc[5], w5, 256, 256, 256);
    k_wprep_fc<<<(131072+T-1)/T, T>>>(wf[0], wf0d, 131072);
    k_wprep_fc<<<(262144+T-1)/T, T>>>(wf[1], wf1d, 262144);
    k_wprep_fc<<<(5120  +T-1)/T, T>>>(wf[2], wf2d, 5120);
    const int cch[6] = {64,64,128,128,256,256};
    for (int i=0;i<6;i++)
        k_bnprep<<<1, 256>>>(bnc[i], cch[i], bns+i*256, bnm+i*256, bnb+i*256);
    k_bnprep<<<2, 256>>>(bnf[0], 512, fns,     fnm,     fnb);
    k_bnprep<<<2, 256>>>(bnf[1], 512, fns+512, fnm+512, fnb+512);

    // ---- conv pipeline
    {   // conv0: 3->64, 32x32 -> 30x30
        const int SM = 64*9*4 + 1*32*32*4;
        k_conv<4,64,64,32,32,1,true><<<dim3(1024,1), T, SM>>>(a0, w0, bns, bnm, bnb, c0);
    }
    {   // conv1: 64->64, 30x30 -> 28x28
        const int SM = 64*9*64 + 1*30*30*64;   // 94464
        cudaFuncSetAttribute(k_conv<64,64,64,30,30,1,false>,
                             cudaFuncAttributeMaxDynamicSharedMemorySize, SM);
        k_conv<64,64,64,30,30,1,false><<<dim3(1024,1), T, SM>>>(c0, w1, bns+256, bnm+256, bnb+256, c1);
    }
    k_pool<64,28,28><<<(BSZ*14*14*16+T-1)/T, T>>>(c1, p1);
    {   // conv2: 64->128, 14x14 -> 12x12
        const int SM = 128*9*64 + 2*14*14*64;  // 98816
        cudaFuncSetAttribute(k_conv<64,128,128,14,14,2,false>,
                             cudaFuncAttributeMaxDynamicSharedMemorySize, SM);
        k_conv<64,128,128,14,14,2,false><<<dim3(512,1), T, SM>>>(p1, w2, bns+512, bnm+512, bnb+512, c2);
    }
    {   // conv3: 128->128, 12x12 -> 10x10  (2 oc tiles)
        const int SM = 64*9*128 + 2*12*12*128; // 110592
        cudaFuncSetAttribute(k_conv<128,128,64,12,12,2,false>,
                             cudaFuncAttributeMaxDynamicSharedMemorySize, SM);
        k_conv<128,128,64,12,12,2,false><<<dim3(512,2), T, SM>>>(c2, w3, bns+768, bnm+768, bnb+768, c3);
    }
    k_pool<128,10,10><<<(BSZ*5*5*32+T-1)/T, T>>>(c3, p3);
    {   // conv4: 128->256, 5x5 -> 3x3  (4 oc tiles, 8 imgs/block)
        const int SM = 64*9*128 + 8*5*5*128;   // 99328
        cudaFuncSetAttribute(k_conv<128,256,64,5,5,8,false>,
                             cudaFuncAttributeMaxDynamicSharedMemorySize, SM);
        k_conv<128,256,64,5,5,8,false><<<dim3(128,4), T, SM>>>(p3, w4, bns+1024, bnm+1024, bnb+1024, c4);
    }
    // conv5 (3x3x256 -> 256, 1x1 spatial) == FC with FI=2304
    k_fc<2304,256,8><<<BSZ/8, T>>>(c4, w5, bns+1280, bnm+1280, bnb+1280, c5);
    // FC head
    k_fc<256,512,8><<<BSZ/8, T>>>(c5, wf0d, fns,     fnm,     fnb,     f0);
    k_fc<512,512,8><<<BSZ/8, T>>>(f0, wf1d, fns+512, fnm+512, fnb+512, f1);
    k_fc_last<<<BSZ, T>>>(f1, wf2d, tn, (float*)d_out);
}

// round 3
// speedup vs baseline: 2.0166x; 2.0166x over previous
#include <cuda_runtime.h>
#include <cstdint>

#define BSZ 1024

// ---------------- static device buffers ----------------
__device__ int8_t g_a0[BSZ*32*32*4];
__device__ int8_t g_c0[BSZ*30*30*64];
__device__ int8_t g_c1[BSZ*28*28*64];
__device__ int8_t g_p1[BSZ*14*14*64];
__device__ int8_t g_c2[BSZ*12*12*128];
__device__ int8_t g_c3[BSZ*10*10*128];
__device__ int8_t g_p3[BSZ*5*5*128];
__device__ int8_t g_c4[BSZ*3*3*256];
__device__ int8_t g_c5[BSZ*256];
__device__ int8_t g_f0[BSZ*512];
__device__ int8_t g_f1[BSZ*512];

__device__ int8_t g_w0[64*36];        // dense [oc][9*4]
__device__ int8_t g_w1[64*592];       // padded [oc][576+16]
__device__ int8_t g_w2[128*592];
__device__ int8_t g_w3[128*1168];     // padded [oc][1152+16]
__device__ int8_t g_w4[256*1152];     // dense
__device__ int8_t g_w5[256*2304];     // dense
__device__ int8_t g_wf0[512*256];
__device__ int8_t g_wf1[512*512];
__device__ int8_t g_wf2[10*512];

__device__ float g_bns[6*256], g_bnm[6*256], g_bnb[6*256];
__device__ float g_fns[2*512], g_fnm[2*512], g_fnb[2*512];

// ---------------- helpers ----------------
__device__ __forceinline__ int8_t qtern(float y){
    float r = rintf(y);
    r = fminf(fmaxf(r, -1.f), 1.f);
    return (int8_t)r;
}

__device__ __forceinline__ void mma_s8(int* c, int a0,int a1,int a2,int a3,int b0,int b1){
    asm volatile(
        "mma.sync.aligned.m16n8k32.row.col.s32.s8.s8.s32 "
        "{%0,%1,%2,%3},{%4,%5,%6,%7},{%8,%9},{%0,%1,%2,%3};"
        : "+r"(c[0]),"+r"(c[1]),"+r"(c[2]),"+r"(c[3])
        : "r"(a0),"r"(a1),"r"(a2),"r"(a3),"r"(b0),"r"(b1));
}

// ---------------- prep kernels ----------------
__global__ void k_inquant(const float* __restrict__ x, int8_t* __restrict__ out){
    int idx = blockIdx.x*256 + threadIdx.x;
    if (idx >= BSZ*1024) return;
    int b = idx >> 10, p = idx & 1023;
    const float* xb = x + (size_t)b*3072;
    char4 r; float v;
    v = rintf(xb[p]     *128.f); v = fminf(fmaxf(v,-128.f),127.f); r.x = (signed char)v;
    v = rintf(xb[1024+p]*128.f); v = fminf(fmaxf(v,-128.f),127.f); r.y = (signed char)v;
    v = rintf(xb[2048+p]*128.f); v = fminf(fmaxf(v,-128.f),127.f); r.z = (signed char)v;
    r.w = 0;
    ((char4*)out)[idx] = r;
}

// OIHW float -> [oc][k][CIP] int8 ternary at row stride KP bytes
__global__ void k_wprep_conv(const float* __restrict__ src, int8_t* __restrict__ dst,
                             int CI, int CIP, int CO, int KP){
    int idx = blockIdx.x*256 + threadIdx.x;
    int tot = CO*9*CIP;
    if (idx >= tot) return;
    int c  = idx % CIP;
    int k  = (idx / CIP) % 9;
    int oc = idx / (9*CIP);
    int8_t q = 0;
    if (c < CI){
        float v = src[(size_t)(oc*CI + c)*9 + k];
        float r = rintf(v);
        r = fminf(fmaxf(r, -1.f), 1.f);
        q = (int8_t)r;
    }
    dst[(size_t)oc*KP + k*CIP + c] = q;
}

__global__ void k_wprep_fc(const float* __restrict__ src, int8_t* __restrict__ dst, int n){
    int idx = blockIdx.x*256 + threadIdx.x;
    if (idx >= n) return;
    float r = rintf(src[idx]);
    r = fminf(fmaxf(r, -1.f), 1.f);
    dst[idx] = (int8_t)r;
}

__global__ void k_bnprep(const float* __restrict__ p, int C,
                         float* __restrict__ s, float* __restrict__ m, float* __restrict__ b){
    int c = blockIdx.x*256 + threadIdx.x;
    if (c >= C) return;
    s[c] = p[c] / sqrtf(p[3*C + c] + 1e-4f);
    m[c] = p[2*C + c];
    b[c] = p[C + c];
}

// ---------------- implicit-GEMM conv via mma.sync (IMMA s8) ----------------
// One image per CTA. SMEM: image [INPIX][CIN+16] + all weights [COUT][9*CIN+16].
// 8 warps = 4 m16-tiles x 2 n-halves. Full K unroll; each k32 chunk sits in one tap.
template<int CIN,int COUT,int HIN,int WIN,int MT>
__global__ void __launch_bounds__(256) k_cmma(
    const int8_t* __restrict__ in, const int8_t* __restrict__ wt,
    const float* __restrict__ bs, const float* __restrict__ bm, const float* __restrict__ bb,
    int8_t* __restrict__ out)
{
    constexpr int HOUT = HIN-2, WOUT = WIN-2;
    constexpr int NPIX = HOUT*WOUT, INPIX = HIN*WIN;
    constexpr int K  = 9*CIN, KP = K+16, SA = CIN+16;
    constexpr int CH = K/32;            // k32 chunks
    constexpr int CPT = CIN/32;         // chunks per tap
    constexpr int NT = COUT/16;         // n8 tiles per warp (warp covers COUT/2)
    constexpr int AW = INPIX*SA;        // act smem bytes

    extern __shared__ int8_t smem[];
    int8_t* s_a = smem;
    int8_t* s_w = smem + AW;

    const int tid  = threadIdx.x;
    const int img  = blockIdx.x;
    const int lane = tid & 31;
    const int warp = tid >> 5;
    const int wm   = warp & 3;          // m16 tile
    const int wn   = warp >> 2;         // n half

    { // act copy with padded row stride
        constexpr int RV = CIN/16;      // int4 per row
        const int4* src = (const int4*)(in + (size_t)img*INPIX*CIN);
        #pragma unroll 4
        for (int i = tid; i < INPIX*RV; i += 256){
            int row = i / RV, j = i % RV;
            ((int4*)s_a)[row*(SA/16) + j] = src[i];
        }
    }
    { // weights (already padded layout in global)
        const int4* src = (const int4*)wt;
        int4* dst = (int4*)s_w;
        #pragma unroll 4
        for (int i = tid; i < COUT*KP/16; i += 256) dst[i] = src[i];
    }
    __syncthreads();

    // per-thread B base byte offset
    const int wb = (wn*(COUT/2) + (lane>>2))*KP + (lane&3)*4;

    for (int mt = 0; mt < MT; mt++){
        const int p0 = mt*64 + wm*16 + (lane>>2);
        const int p1 = p0 + 8;
        const int a0base = ((p0/WOUT)*WIN + (p0%WOUT))*SA + (lane&3)*4;
        const int a1base = ((p1/WOUT)*WIN + (p1%WOUT))*SA + (lane&3)*4;

        int acc[NT][4];
        #pragma unroll
        for (int nt=0; nt<NT; nt++){ acc[nt][0]=acc[nt][1]=acc[nt][2]=acc[nt][3]=0; }

        #pragma unroll
        for (int ch = 0; ch < CH; ch++){
            const int kk = ch / CPT;
            const int cb = (ch % CPT)*32;
            const int aoff = ((kk/3)*WIN + (kk%3))*SA + cb;
            const int A0 = *(const int*)(s_a + a0base + aoff);
            const int A2 = *(const int*)(s_a + a0base + aoff + 16);
            const int A1 = *(const int*)(s_a + a1base + aoff);
            const int A3 = *(const int*)(s_a + a1base + aoff + 16);
            const int woff = ch*32;
            #pragma unroll
            for (int nt=0; nt<NT; nt++){
                const int B0 = *(const int*)(s_w + wb + nt*8*KP + woff);
                const int B1 = *(const int*)(s_w + wb + nt*8*KP + woff + 16);
                mma_s8(acc[nt], A0, A1, A2, A3, B0, B1);
            }
        }

        // epilogue: BN + ternary quant, char2 stores
        #pragma unroll
        for (int nt=0; nt<NT; nt++){
            const int col = wn*(COUT/2) + nt*8 + (lane&3)*2;
            const float s0 = bs[col],   m0 = bm[col],   b0 = bb[col];
            const float s1 = bs[col+1], m1 = bm[col+1], b1 = bb[col+1];
            if (p0 < NPIX){
                char2 o;
                o.x = qtern(((float)acc[nt][0] - m0)*s0 + b0);
                o.y = qtern(((float)acc[nt][1] - m1)*s1 + b1);
                *(char2*)(out + ((size_t)img*NPIX + p0)*COUT + col) = o;
            }
            if (p1 < NPIX){
                char2 o;
                o.x = qtern(((float)acc[nt][2] - m0)*s0 + b0);
                o.y = qtern(((float)acc[nt][3] - m1)*s1 + b1);
                *(char2*)(out + ((size_t)img*NPIX + p1)*COUT + col) = o;
            }
        }
    }
}

// ---------------- dp4a conv (conv0 / conv4) ----------------
template<int CIN,int COUT,int OCT,int HIN,int WIN,int NIMG,bool FIRST>
__global__ void __launch_bounds__(256) k_conv(
    const int8_t* __restrict__ in, const int8_t* __restrict__ wt,
    const float* __restrict__ bs, const float* __restrict__ bm, const float* __restrict__ bb,
    int8_t* __restrict__ out)
{
    constexpr int HOUT = HIN-2, WOUT = WIN-2;
    constexpr int NPIX = HOUT*WOUT, INPIX = HIN*WIN;
    constexpr int NC   = FIRST ? 1 : CIN/16;
    constexpr int NOCG = OCT/16;
    constexpr int WB   = OCT*9*CIN;
    extern __shared__ int8_t smem[];
    int8_t* s_w  = smem;
    int8_t* s_in = smem + WB;

    const int tid  = threadIdx.x;
    const int img0 = blockIdx.x * NIMG;
    const int ocb  = blockIdx.y * OCT;

    {
        const int4* src = (const int4*)(wt + (size_t)ocb*9*CIN);
        int4* dst = (int4*)s_w;
        #pragma unroll 4
        for (int i = tid; i < WB/16; i += 256) dst[i] = src[i];
    }
    if (FIRST){
        const int* src = (const int*)(in + (size_t)img0*INPIX*4);
        int* dst = (int*)s_in;
        for (int i = tid; i < NIMG*INPIX; i += 256) dst[i] = src[i];
    } else {
        const int4* src = (const int4*)(in + (size_t)img0*INPIX*CIN);
        int4* dst = (int4*)s_in;
        for (int i = tid; i < NIMG*INPIX*NC; i += 256){
            int c  = i % NC;
            int p  = i / NC;
            int im = p / INPIX;
            int pp = p % INPIX;
            dst[(im*NC + c)*INPIX + pp] = src[i];
        }
    }
    __syncthreads();

    constexpr int TOT = NIMG*NPIX*NOCG;
    for (int t = tid; t < TOT; t += 256){
        int pix = t % NPIX;
        int r2  = t / NPIX;
        int ocg = r2 % NOCG;
        int im  = r2 / NOCG;
        int oy = pix / WOUT, ox = pix % WOUT;
        int acc[16];
        #pragma unroll
        for (int j=0;j<16;j++) acc[j]=0;
        const int8_t* wb_ = s_w + (size_t)ocg*16*9*CIN;

        #pragma unroll 1
        for (int ky=0; ky<3; ky++){
            #pragma unroll
            for (int kx=0; kx<3; kx++){
                const int p  = (oy+ky)*WIN + ox + kx;
                const int kk = ky*3 + kx;
                if (FIRST){
                    const int a = ((const int*)s_in)[im*INPIX + p];
                    #pragma unroll
                    for (int j=0;j<16;j++){
                        int w = *(const int*)(wb_ + (j*9 + kk)*4);
                        acc[j] = __dp4a(a, w, acc[j]);
                    }
                } else {
                    #pragma unroll 2
                    for (int c=0;c<NC;c++){
                        const int4 a = ((const int4*)s_in)[(im*NC + c)*INPIX + p];
                        #pragma unroll
                        for (int j=0;j<16;j++){
                            const int4 w = *(const int4*)(wb_ + (j*9 + kk)*CIN + c*16);
                            acc[j] = __dp4a(a.x, w.x, acc[j]);
                            acc[j] = __dp4a(a.y, w.y, acc[j]);
                            acc[j] = __dp4a(a.z, w.z, acc[j]);
                            acc[j] = __dp4a(a.w, w.w, acc[j]);
                        }
                    }
                }
            }
        }
        union { int8_t b[16]; int4 v; } q;
        #pragma unroll
        for (int j=0;j<16;j++){
            int oc = ocb + ocg*16 + j;
            float v = (float)acc[j];
            if (FIRST) v *= (1.0f/128.0f);
            float y = (v - bm[oc]) * bs[oc] + bb[oc];
            q.b[j] = qtern(y);
        }
        *(int4*)(out + ((size_t)(img0+im)*NPIX + pix)*COUT + ocb + ocg*16) = q.v;
    }
}

// ---------------- pool ----------------
template<int C,int HIN,int WIN>
__global__ void k_pool(const int8_t* __restrict__ in, int8_t* __restrict__ out){
    constexpr int HO=HIN/2, WO=WIN/2, C4=C/4;
    constexpr int TOT = BSZ*HO*WO*C4;
    int idx = blockIdx.x*256 + threadIdx.x;
    if (idx >= TOT) return;
    int c4 = idx % C4;
    int rr = idx / C4;
    int ox = rr % WO; rr /= WO;
    int oy = rr % HO;
    int b  = rr / HO;
    const int8_t* base = in + ((size_t)(b*HIN + 2*oy)*WIN + 2*ox)*C + c4*4;
    char4 a0 = *(const char4*)base;
    char4 a1 = *(const char4*)(base + C);
    char4 a2 = *(const char4*)(base + (size_t)WIN*C);
    char4 a3 = *(const char4*)(base + (size_t)WIN*C + C);
    char4 o;
    o.x = qtern((float)(a0.x+a1.x+a2.x+a3.x) * 0.25f);
    o.y = qtern((float)(a0.y+a1.y+a2.y+a3.y) * 0.25f);
    o.z = qtern((float)(a0.z+a1.z+a2.z+a3.z) * 0.25f);
    o.w = qtern((float)(a0.w+a1.w+a2.w+a3.w) * 0.25f);
    ((char4*)out)[idx] = o;
}

// ---------------- FC ----------------
template<int FI,int FO,int BT>
__global__ void __launch_bounds__(256) k_fc(
    const int8_t* __restrict__ in, const int8_t* __restrict__ wt,
    const float* __restrict__ bs, const float* __restrict__ bm, const float* __restrict__ bb,
    int8_t* __restrict__ out)
{
    __shared__ int8_t s_a[BT*FI];
    const int b0 = blockIdx.x*BT, tid = threadIdx.x;
    const int4* src = (const int4*)(in + (size_t)b0*FI);
    for (int i = tid; i < BT*FI/16; i += 256) ((int4*)s_a)[i] = src[i];
    __syncthreads();
    for (int oc = tid; oc < FO; oc += 256){
        int acc[BT];
        #pragma unroll
        for (int j=0;j<BT;j++) acc[j]=0;
        const int4* wr = (const int4*)(wt + (size_t)oc*FI);
        #pragma unroll 4
        for (int c=0;c<FI/16;c++){
            int4 w = wr[c];
            #pragma unroll
            for (int j=0;j<BT;j++){
                int4 a = ((const int4*)s_a)[j*(FI/16)+c];
                acc[j]=__dp4a(a.x,w.x,acc[j]);
                acc[j]=__dp4a(a.y,w.y,acc[j]);
                acc[j]=__dp4a(a.z,w.z,acc[j]);
                acc[j]=__dp4a(a.w,w.w,acc[j]);
            }
        }
        #pragma unroll
        for (int j=0;j<BT;j++){
            float y = ((float)acc[j] - bm[oc]) * bs[oc] + bb[oc];
            out[(size_t)(b0+j)*FO + oc] = qtern(y);
        }
    }
}

__global__ void k_fc_last(const int8_t* __restrict__ in, const int8_t* __restrict__ wt,
                          const float* __restrict__ tn, float* __restrict__ out){
    __shared__ int8_t s_a[512];
    int b = blockIdx.x, tid = threadIdx.x;
    for (int i = tid; i < 32; i += 256)
        ((int4*)s_a)[i] = ((const int4*)(in + (size_t)b*512))[i];
    __syncthreads();
    if (tid < 10){
        const int4* wr = (const int4*)(wt + (size_t)tid*512);
        int acc = 0;
        #pragma unroll 8
        for (int c=0;c<32;c++){
            int4 a = ((const int4*)s_a)[c];
            int4 w = wr[c];
            acc=__dp4a(a.x,w.x,acc); acc=__dp4a(a.y,w.y,acc);
            acc=__dp4a(a.z,w.z,acc); acc=__dp4a(a.w,w.w,acc);
        }
        float y = ((float)acc - tn[2]) / sqrtf(tn[3] + 1e-4f) * tn[0] + tn[1];
        out[b*10 + tid] = y;
    }
}

// ---------------- host ----------------
extern "C" void kernel_launch(void* const* d_in, const int* in_sizes, int n_in,
                              void* d_out, int out_size)
{
    const float *x=0, *wc[6]={0,0,0,0,0,0}, *bnc[6]={0,0,0,0,0,0};
    const float *wf[3]={0,0,0}, *bnf[2]={0,0}, *tn=0;
    int n256=0, n512=0, n1024=0, n2048=0;
    for (int i=0;i<n_in;i++){
        const float* p = (const float*)d_in[i];
        switch (in_sizes[i]){
            case 3145728: x = p; break;
            case 1728:    wc[0]=p; break;
            case 36864:   wc[1]=p; break;
            case 73728:   wc[2]=p; break;
            case 147456:  wc[3]=p; break;
            case 294912:  wc[4]=p; break;
            case 589824:  wc[5]=p; break;
            case 131072:  wf[0]=p; break;
            case 262144:  wf[1]=p; break;
            case 5120:    wf[2]=p; break;
            case 256:     if(n256 <2) bnc[0+n256++ ]=p; break;
            case 512:     if(n512 <2) bnc[2+n512++ ]=p; break;
            case 1024:    if(n1024<2) bnc[4+n1024++]=p; break;
            case 2048:    if(n2048<2) bnf[n2048++  ]=p; break;
            case 4:       tn = p; break;
            default: break;
        }
    }

    int8_t *a0,*c0,*c1,*p1,*c2,*c3,*p3,*c4,*c5,*f0,*f1;
    int8_t *w0,*w1,*w2,*w3,*w4,*w5,*wf0d,*wf1d,*wf2d;
    float *bns,*bnm,*bnb,*fns,*fnm,*fnb;
    cudaGetSymbolAddress((void**)&a0, g_a0);  cudaGetSymbolAddress((void**)&c0, g_c0);
    cudaGetSymbolAddress((void**)&c1, g_c1);  cudaGetSymbolAddress((void**)&p1, g_p1);
    cudaGetSymbolAddress((void**)&c2, g_c2);  cudaGetSymbolAddress((void**)&c3, g_c3);
    cudaGetSymbolAddress((void**)&p3, g_p3);  cudaGetSymbolAddress((void**)&c4, g_c4);
    cudaGetSymbolAddress((void**)&c5, g_c5);  cudaGetSymbolAddress((void**)&f0, g_f0);
    cudaGetSymbolAddress((void**)&f1, g_f1);
    cudaGetSymbolAddress((void**)&w0, g_w0);  cudaGetSymbolAddress((void**)&w1, g_w1);
    cudaGetSymbolAddress((void**)&w2, g_w2);  cudaGetSymbolAddress((void**)&w3, g_w3);
    cudaGetSymbolAddress((void**)&w4, g_w4);  cudaGetSymbolAddress((void**)&w5, g_w5);
    cudaGetSymbolAddress((void**)&wf0d, g_wf0); cudaGetSymbolAddress((void**)&wf1d, g_wf1);
    cudaGetSymbolAddress((void**)&wf2d, g_wf2);
    cudaGetSymbolAddress((void**)&bns, g_bns); cudaGetSymbolAddress((void**)&bnm, g_bnm);
    cudaGetSymbolAddress((void**)&bnb, g_bnb);
    cudaGetSymbolAddress((void**)&fns, g_fns); cudaGetSymbolAddress((void**)&fnm, g_fnm);
    cudaGetSymbolAddress((void**)&fnb, g_fnb);

    const int T = 256;
    // ---- prep
    k_inquant<<<(BSZ*1024+T-1)/T, T>>>(x, a0);
    k_wprep_conv<<<(64*9*4   +T-1)/T, T>>>(wc[0], w0, 3,   4,   64,  36);
    k_wprep_conv<<<(64*9*64  +T-1)/T, T>>>(wc[1], w1, 64,  64,  64,  592);
    k_wprep_conv<<<(128*9*64 +T-1)/T, T>>>(wc[2], w2, 64,  64,  128, 592);
    k_wprep_conv<<<(128*9*128+T-1)/T, T>>>(wc[3], w3, 128, 128, 128, 1168);
    k_wprep_conv<<<(256*9*128+T-1)/T, T>>>(wc[4], w4, 128, 128, 256, 1152);
    k_wprep_conv<<<(256*9*256+T-1)/T, T>>>(wc[5], w5, 256, 256, 256, 2304);
    k_wprep_fc<<<(131072+T-1)/T, T>>>(wf[0], wf0d, 131072);
    k_wprep_fc<<<(262144+T-1)/T, T>>>(wf[1], wf1d, 262144);
    k_wprep_fc<<<(5120  +T-1)/T, T>>>(wf[2], wf2d, 5120);
    const int cch[6] = {64,64,128,128,256,256};
    for (int i=0;i<6;i++)
        k_bnprep<<<1, 256>>>(bnc[i], cch[i], bns+i*256, bnm+i*256, bnb+i*256);
    k_bnprep<<<2, 256>>>(bnf[0], 512, fns,     fnm,     fnb);
    k_bnprep<<<2, 256>>>(bnf[1], 512, fns+512, fnm+512, fnb+512);

    // ---- conv pipeline
    {   // conv0: 3->64, 32x32 -> 30x30 (dp4a)
        const int SM = 64*9*4 + 1*32*32*4;
        k_conv<4,64,64,32,32,1,true><<<dim3(1024,1), T, SM>>>(a0, w0, bns, bnm, bnb, c0);
    }
    {   // conv1: 64->64, 30x30 -> 28x28 (mma)
        const int SM = 900*80 + 64*592;          // 109888
        cudaFuncSetAttribute(k_cmma<64,64,30,30,13>,
                             cudaFuncAttributeMaxDynamicSharedMemorySize, SM);
        k_cmma<64,64,30,30,13><<<1024, T, SM>>>(c0, w1, bns+256, bnm+256, bnb+256, c1);
    }
    k_pool<64,28,28><<<(BSZ*14*14*16+T-1)/T, T>>>(c1, p1);
    {   // conv2: 64->128, 14x14 -> 12x12 (mma)
        const int SM = 196*80 + 128*592;         // 91456
        cudaFuncSetAttribute(k_cmma<64,128,14,14,3>,
                             cudaFuncAttributeMaxDynamicSharedMemorySize, SM);
        k_cmma<64,128,14,14,3><<<1024, T, SM>>>(p1, w2, bns+512, bnm+512, bnb+512, c2);
    }
    {   // conv3: 128->128, 12x12 -> 10x10 (mma)
        const int SM = 144*144 + 128*1168;       // 170240
        cudaFuncSetAttribute(k_cmma<128,128,12,12,2>,
                             cudaFuncAttributeMaxDynamicSharedMemorySize, SM);
        k_cmma<128,128,12,12,2><<<1024, T, SM>>>(c2, w3, bns+768, bnm+768, bnb+768, c3);
    }
    k_pool<128,10,10><<<(BSZ*5*5*32+T-1)/T, T>>>(c3, p3);
    {   // conv4: 128->256, 5x5 -> 3x3 (dp4a)
        const int SM = 64*9*128 + 8*5*5*128;     // 99328
        cudaFuncSetAttribute(k_conv<128,256,64,5,5,8,false>,
                             cudaFuncAttributeMaxDynamicSharedMemorySize, SM);
        k_conv<128,256,64,5,5,8,false><<<dim3(128,4), T, SM>>>(p3, w4, bns+1024, bnm+1024, bnb+1024, c4);
    }
    // conv5 (1x1 spatial) == FC with FI=2304
    k_fc<2304,256,8><<<BSZ/8, T>>>(c4, w5, bns+1280, bnm+1280, bnb+1280, c5);
    // FC head
    k_fc<256,512,8><<<BSZ/8, T>>>(c5, wf0d, fns,     fnm,     fnb,     f0);
    k_fc<512,512,8><<<BSZ/8, T>>>(f0, wf1d, fns+512, fnm+512, fnb+512, f1);
    k_fc_last<<<BSZ, T>>>(f1, wf2d, tn, (float*)d_out);
}

// round 4
// speedup vs baseline: 2.8742x; 1.4252x over previous
#include <cuda_runtime.h>
#include <cstdint>

#define BSZ 1024

// ---------------- static device buffers ----------------
__device__ int8_t g_a0[BSZ*32*32*4];
__device__ int8_t g_c0[BSZ*30*30*64];
__device__ int8_t g_c1[BSZ*28*28*64];
__device__ int8_t g_p1[BSZ*14*14*64];
__device__ int8_t g_c2[BSZ*12*12*128];
__device__ int8_t g_c3[BSZ*10*10*128];
__device__ int8_t g_p3[BSZ*5*5*128];
__device__ int8_t g_c4[BSZ*3*3*256];
__device__ int8_t g_c5[BSZ*256];
__device__ int8_t g_f0[BSZ*512];
__device__ int8_t g_f1[BSZ*512];

__device__ int8_t g_w0[64*36];        // dense [oc][9*4]  (dp4a conv0)
__device__ int8_t g_w1[64*592];       // padded [oc][576+16]
__device__ int8_t g_w2[128*592];
__device__ int8_t g_w3[128*1168];
__device__ int8_t g_w4[256*1168];     // padded (mma)
__device__ int8_t g_w5[256*2304];     // dense (fc path)
__device__ int8_t g_wf0[512*256];
__device__ int8_t g_wf1[512*512];
__device__ int8_t g_wf2[10*512];

__device__ float g_bns[6*256], g_bnm[6*256], g_bnb[6*256];
__device__ float g_fns[2*512], g_fnm[2*512], g_fnb[2*512];

// ---------------- helpers ----------------
__device__ __forceinline__ int8_t qtern(float y){
    float r = rintf(y);
    r = fminf(fmaxf(r, -1.f), 1.f);
    return (int8_t)r;
}

__device__ __forceinline__ void mma_s8(int* c, int a0,int a1,int a2,int a3,int b0,int b1){
    asm volatile(
        "mma.sync.aligned.m16n8k32.row.col.s32.s8.s8.s32 "
        "{%0,%1,%2,%3},{%4,%5,%6,%7},{%8,%9},{%0,%1,%2,%3};"
        : "+r"(c[0]),"+r"(c[1]),"+r"(c[2]),"+r"(c[3])
        : "r"(a0),"r"(a1),"r"(a2),"r"(a3),"r"(b0),"r"(b1));
}

__device__ __forceinline__ void ldsm_x4(uint32_t addr, int& r0,int& r1,int& r2,int& r3){
    asm volatile("ldmatrix.sync.aligned.m8n8.x4.shared.b16 {%0,%1,%2,%3}, [%4];"
        : "=r"(r0),"=r"(r1),"=r"(r2),"=r"(r3) : "r"(addr));
}
__device__ __forceinline__ void ldsm_x2(uint32_t addr, int& r0,int& r1){
    asm volatile("ldmatrix.sync.aligned.m8n8.x2.shared.b16 {%0,%1}, [%2];"
        : "=r"(r0),"=r"(r1) : "r"(addr));
}

__device__ __forceinline__ int8_t wq(float v){
    float r = rintf(v);
    r = fminf(fmaxf(r, -1.f), 1.f);
    return (int8_t)r;
}

// ---------------- merged prep kernels ----------------
__global__ void k_inquant(const float* __restrict__ x, int8_t* __restrict__ out){
    int idx = blockIdx.x*256 + threadIdx.x;
    if (idx >= BSZ*1024) return;
    int b = idx >> 10, p = idx & 1023;
    const float* xb = x + (size_t)b*3072;
    char4 r; float v;
    v = rintf(xb[p]     *128.f); v = fminf(fmaxf(v,-128.f),127.f); r.x = (signed char)v;
    v = rintf(xb[1024+p]*128.f); v = fminf(fmaxf(v,-128.f),127.f); r.y = (signed char)v;
    v = rintf(xb[2048+p]*128.f); v = fminf(fmaxf(v,-128.f),127.f); r.z = (signed char)v;
    r.w = 0;
    ((char4*)out)[idx] = r;
}

__device__ __forceinline__ void wq_conv(const float* __restrict__ src, int8_t* dst,
                                        int CI, int CIP, int KP, int idx){
    int c  = idx % CIP;
    int k  = (idx / CIP) % 9;
    int oc = idx / (9*CIP);
    int8_t q = 0;
    if (c < CI) q = wq(src[(size_t)(oc*CI + c)*9 + k]);
    dst[(size_t)oc*KP + k*CIP + c] = q;
}

__global__ void k_wprep_all(const float* wc0,const float* wc1,const float* wc2,
                            const float* wc3,const float* wc4,const float* wc5,
                            const float* wf0,const float* wf1,const float* wf2){
    int idx = blockIdx.x*256 + threadIdx.x;
    if (idx < 2304)  { wq_conv(wc0, g_w0, 3,  4,  36,  idx); return; }  idx -= 2304;
    if (idx < 36864) { wq_conv(wc1, g_w1, 64, 64, 592, idx); return; }  idx -= 36864;
    if (idx < 73728) { wq_conv(wc2, g_w2, 64, 64, 592, idx); return; }  idx -= 73728;
    if (idx < 147456){ wq_conv(wc3, g_w3, 128,128,1168,idx); return; }  idx -= 147456;
    if (idx < 294912){ wq_conv(wc4, g_w4, 128,128,1168,idx); return; }  idx -= 294912;
    if (idx < 589824){ wq_conv(wc5, g_w5, 256,256,2304,idx); return; }  idx -= 589824;
    if (idx < 131072){ g_wf0[idx] = wq(wf0[idx]); return; }             idx -= 131072;
    if (idx < 262144){ g_wf1[idx] = wq(wf1[idx]); return; }             idx -= 262144;
    if (idx < 5120)  { g_wf2[idx] = wq(wf2[idx]); }
}

__global__ void k_bnprep_conv(const float* b0,const float* b1,const float* b2,
                              const float* b3,const float* b4,const float* b5){
    const float* srcs[6] = {b0,b1,b2,b3,b4,b5};
    const int    chs [6] = {64,64,128,128,256,256};
    int seg = blockIdx.x, c = threadIdx.x;
    int C = chs[seg];
    if (c >= C) return;
    const float* p = srcs[seg];
    g_bns[seg*256+c] = p[c] / sqrtf(p[3*C+c] + 1e-4f);
    g_bnm[seg*256+c] = p[2*C+c];
    g_bnb[seg*256+c] = p[C+c];
}

__global__ void k_bnprep_fc(const float* b0,const float* b1){
    const float* p = blockIdx.x ? b1 : b0;
    int off = blockIdx.x*512, c = threadIdx.x;   // blockDim = 512
    g_fns[off+c] = p[c] / sqrtf(p[1536+c] + 1e-4f);
    g_fnm[off+c] = p[1024+c];
    g_fnb[off+c] = p[512+c];
}

// ---------------- implicit-GEMM conv via ldmatrix + mma.sync ----------------
// 8 warps = 2 m-warps (32 rows each: 2x m16) x 4 n-warps (OCT/4 oc each).
// SMEM: acts [NIMG][INPIX][CIN+16] + weights [OCT][9*CIN+16].
template<int CIN,int COUT,int OCT,int HIN,int WIN,int NIMG>
__global__ void __launch_bounds__(256) k_cmma(
    const int8_t* __restrict__ in, const int8_t* __restrict__ wt,
    const float* __restrict__ bs, const float* __restrict__ bm, const float* __restrict__ bb,
    int8_t* __restrict__ out)
{
    constexpr int HOUT = HIN-2, WOUT = WIN-2;
    constexpr int NPIX = HOUT*WOUT, INPIX = HIN*WIN;
    constexpr int K  = 9*CIN, KP = K+16, SA = CIN+16;
    constexpr int CH = K/32;
    constexpr int CPT = CIN/32;
    constexpr int NT = OCT/32;          // n8 tiles per warp
    constexpr int AW = NIMG*INPIX*SA;
    constexpr int NROWS = NIMG*NPIX;
    constexpr int MT = (NROWS + 63)/64;

    extern __shared__ int8_t smem[];
    int8_t* s_a = smem;
    int8_t* s_w = smem + AW;

    const int tid  = threadIdx.x;
    const int img0 = blockIdx.x * NIMG;
    const int ocb  = blockIdx.y * OCT;
    const int lane = tid & 31;
    const int warp = tid >> 5;
    const int wm   = warp & 1;
    const int wn   = warp >> 1;
    const int ocw  = wn * (OCT/4);

    { // act copy with padded row stride
        constexpr int RV = CIN/16;
        const int4* src = (const int4*)(in + (size_t)img0*INPIX*CIN);
        #pragma unroll 4
        for (int i = tid; i < NIMG*INPIX*RV; i += 256){
            int row = i / RV, j = i % RV;
            ((int4*)s_a)[row*(SA/16) + j] = src[i];
        }
    }
    { // weight tile
        const int4* src = (const int4*)(wt + (size_t)ocb*KP);
        int4* dst = (int4*)s_w;
        #pragma unroll 4
        for (int i = tid; i < OCT*KP/16; i += 256) dst[i] = src[i];
    }
    __syncthreads();

    const uint32_t s_a32 = (uint32_t)__cvta_generic_to_shared(s_a);
    const uint32_t s_w32 = (uint32_t)__cvta_generic_to_shared(s_w);

    // B ldmatrix addresses (fixed per warp)
    uint32_t baddr[NT];
    #pragma unroll
    for (int nt=0; nt<NT; nt++)
        baddr[nt] = s_w32 + (uint32_t)((ocw + nt*8 + (lane&7))*KP + ((lane>>3)&1)*16);

    // hoisted BN params
    float hs0[NT],hs1[NT],hm0[NT],hm1[NT],hb0[NT],hb1[NT];
    #pragma unroll
    for (int nt=0; nt<NT; nt++){
        int col = ocb + ocw + nt*8 + (lane&3)*2;
        hs0[nt]=bs[col];   hm0[nt]=bm[col];   hb0[nt]=bb[col];
        hs1[nt]=bs[col+1]; hm1[nt]=bm[col+1]; hb1[nt]=bb[col+1];
    }

    const int laneR = lane & 15;
    const int laneC = (lane >> 4) * 16;

    for (int mt = 0; mt < MT; mt++){
        const int rbase = mt*64 + wm*32;

        uint32_t aA[2];
        #pragma unroll
        for (int t=0; t<2; t++){
            int r = rbase + 16*t + laneR;
            if (r >= NROWS) r = 0;
            int im  = r / NPIX;
            int pix = r - im*NPIX;
            int py  = pix / WOUT;
            int px  = pix - py*WOUT;
            aA[t] = s_a32 + (uint32_t)((im*INPIX + py*WIN + px)*SA + laneC);
        }

        int acc[2][NT][4];
        #pragma unroll
        for (int t=0;t<2;t++)
            #pragma unroll
            for (int nt=0;nt<NT;nt++){ acc[t][nt][0]=acc[t][nt][1]=acc[t][nt][2]=acc[t][nt][3]=0; }

        #pragma unroll
        for (int ch = 0; ch < CH; ch++){
            const int kk = ch / CPT;
            const int cb = (ch % CPT)*32;
            const int aoff = ((kk/3)*WIN + (kk%3))*SA + cb;
            int a0,a1,a2,a3,a4,a5,a6,a7;
            ldsm_x4(aA[0]+aoff, a0,a1,a2,a3);
            ldsm_x4(aA[1]+aoff, a4,a5,a6,a7);
            #pragma unroll
            for (int nt=0; nt<NT; nt++){
                int b0,b1;
                ldsm_x2(baddr[nt] + ch*32, b0,b1);
                mma_s8(acc[0][nt], a0,a1,a2,a3, b0,b1);
                mma_s8(acc[1][nt], a4,a5,a6,a7, b0,b1);
            }
        }

        // epilogue
        #pragma unroll
        for (int t=0; t<2; t++){
            const int pa = rbase + 16*t + (lane>>2);
            const int pb = pa + 8;
            int ia = pa / NPIX, xa = pa - ia*NPIX;
            int ib = pb / NPIX, xb = pb - ib*NPIX;
            int8_t* oa = out + ((size_t)(img0+ia)*NPIX + xa)*COUT + ocb + ocw + (lane&3)*2;
            int8_t* ob = out + ((size_t)(img0+ib)*NPIX + xb)*COUT + ocb + ocw + (lane&3)*2;
            #pragma unroll
            for (int nt=0; nt<NT; nt++){
                if (pa < NROWS){
                    char2 o;
                    o.x = qtern(((float)acc[t][nt][0] - hm0[nt])*hs0[nt] + hb0[nt]);
                    o.y = qtern(((float)acc[t][nt][1] - hm1[nt])*hs1[nt] + hb1[nt]);
                    *(char2*)(oa + nt*8) = o;
                }
                if (pb < NROWS){
                    char2 o;
                    o.x = qtern(((float)acc[t][nt][2] - hm0[nt])*hs0[nt] + hb0[nt]);
                    o.y = qtern(((float)acc[t][nt][3] - hm1[nt])*hs1[nt] + hb1[nt]);
                    *(char2*)(ob + nt*8) = o;
                }
            }
        }
    }
}

// ---------------- dp4a conv (conv0 only) ----------------
template<int CIN,int COUT,int OCT,int HIN,int WIN,int NIMG,bool FIRST>
__global__ void __launch_bounds__(256) k_conv(
    const int8_t* __restrict__ in, const int8_t* __restrict__ wt,
    const float* __restrict__ bs, const float* __restrict__ bm, const float* __restrict__ bb,
    int8_t* __restrict__ out)
{
    constexpr int HOUT = HIN-2, WOUT = WIN-2;
    constexpr int NPIX = HOUT*WOUT, INPIX = HIN*WIN;
    constexpr int NOCG = OCT/16;
    constexpr int WB   = OCT*9*CIN;
    extern __shared__ int8_t smem[];
    int8_t* s_w  = smem;
    int8_t* s_in = smem + WB;

    const int tid  = threadIdx.x;
    const int img0 = blockIdx.x * NIMG;
    const int ocb  = blockIdx.y * OCT;

    {
        const int4* src = (const int4*)(wt + (size_t)ocb*9*CIN);
        int4* dst = (int4*)s_w;
        #pragma unroll 4
        for (int i = tid; i < WB/16; i += 256) dst[i] = src[i];
    }
    {
        const int* src = (const int*)(in + (size_t)img0*INPIX*4);
        int* dst = (int*)s_in;
        for (int i = tid; i < NIMG*INPIX; i += 256) dst[i] = src[i];
    }
    __syncthreads();

    constexpr int TOT = NIMG*NPIX*NOCG;
    for (int t = tid; t < TOT; t += 256){
        int pix = t % NPIX;
        int r2  = t / NPIX;
        int ocg = r2 % NOCG;
        int im  = r2 / NOCG;
        int oy = pix / WOUT, ox = pix % WOUT;
        int acc[16];
        #pragma unroll
        for (int j=0;j<16;j++) acc[j]=0;
        const int8_t* wb_ = s_w + (size_t)ocg*16*9*CIN;

        #pragma unroll 1
        for (int ky=0; ky<3; ky++){
            #pragma unroll
            for (int kx=0; kx<3; kx++){
                const int p  = (oy+ky)*WIN + ox + kx;
                const int kk = ky*3 + kx;
                const int a = ((const int*)s_in)[im*INPIX + p];
                #pragma unroll
                for (int j=0;j<16;j++){
                    int w = *(const int*)(wb_ + (j*9 + kk)*4);
                    acc[j] = __dp4a(a, w, acc[j]);
                }
            }
        }
        union { int8_t b[16]; int4 v; } q;
        #pragma unroll
        for (int j=0;j<16;j++){
            int oc = ocb + ocg*16 + j;
            float v = (float)acc[j] * (1.0f/128.0f);
            float y = (v - bm[oc]) * bs[oc] + bb[oc];
            q.b[j] = qtern(y);
        }
        *(int4*)(out + ((size_t)(img0+im)*NPIX + pix)*COUT + ocb + ocg*16) = q.v;
    }
}

// ---------------- pool ----------------
template<int C,int HIN,int WIN>
__global__ void k_pool(const int8_t* __restrict__ in, int8_t* __restrict__ out){
    constexpr int HO=HIN/2, WO=WIN/2, C4=C/4;
    constexpr int TOT = BSZ*HO*WO*C4;
    int idx = blockIdx.x*256 + threadIdx.x;
    if (idx >= TOT) return;
    int c4 = idx % C4;
    int rr = idx / C4;
    int ox = rr % WO; rr /= WO;
    int oy = rr % HO;
    int b  = rr / HO;
    const int8_t* base = in + ((size_t)(b*HIN + 2*oy)*WIN + 2*ox)*C + c4*4;
    char4 a0 = *(const char4*)base;
    char4 a1 = *(const char4*)(base + C);
    char4 a2 = *(const char4*)(base + (size_t)WIN*C);
    char4 a3 = *(const char4*)(base + (size_t)WIN*C + C);
    char4 o;
    o.x = qtern((float)(a0.x+a1.x+a2.x+a3.x) * 0.25f);
    o.y = qtern((float)(a0.y+a1.y+a2.y+a3.y) * 0.25f);
    o.z = qtern((float)(a0.z+a1.z+a2.z+a3.z) * 0.25f);
    o.w = qtern((float)(a0.w+a1.w+a2.w+a3.w) * 0.25f);
    ((char4*)out)[idx] = o;
}

// ---------------- FC (dp4a) ----------------
template<int FI,int FO,int BT>
__global__ void __launch_bounds__(256) k_fc(
    const int8_t* __restrict__ in, const int8_t* __restrict__ wt,
    const float* __restrict__ bs, const float* __restrict__ bm, const float* __restrict__ bb,
    int8_t* __restrict__ out)
{
    __shared__ int8_t s_a[BT*FI];
    const int b0 = blockIdx.x*BT, tid = threadIdx.x;
    const int4* src = (const int4*)(in + (size_t)b0*FI);
    for (int i = tid; i < BT*FI/16; i += 256) ((int4*)s_a)[i] = src[i];
    __syncthreads();
    for (int oc = tid; oc < FO; oc += 256){
        int acc[BT];
        #pragma unroll
        for (int j=0;j<BT;j++) acc[j]=0;
        const int4* wr = (const int4*)(wt + (size_t)oc*FI);
        #pragma unroll 4
        for (int c=0;c<FI/16;c++){
            int4 w = wr[c];
            #pragma unroll
            for (int j=0;j<BT;j++){
                int4 a = ((const int4*)s_a)[j*(FI/16)+c];
                acc[j]=__dp4a(a.x,w.x,acc[j]);
                acc[j]=__dp4a(a.y,w.y,acc[j]);
                acc[j]=__dp4a(a.z,w.z,acc[j]);
                acc[j]=__dp4a(a.w,w.w,acc[j]);
            }
        }
        #pragma unroll
        for (int j=0;j<BT;j++){
            float y = ((float)acc[j] - bm[oc]) * bs[oc] + bb[oc];
            out[(size_t)(b0+j)*FO + oc] = qtern(y);
        }
    }
}

__global__ void k_fc_last(const int8_t* __restrict__ in, const int8_t* __restrict__ wt,
                          const float* __restrict__ tn, float* __restrict__ out){
    __shared__ int8_t s_a[512];
    int b = blockIdx.x, tid = threadIdx.x;
    for (int i = tid; i < 32; i += 256)
        ((int4*)s_a)[i] = ((const int4*)(in + (size_t)b*512))[i];
    __syncthreads();
    if (tid < 10){
        const int4* wr = (const int4*)(wt + (size_t)tid*512);
        int acc = 0;
        #pragma unroll 8
        for (int c=0;c<32;c++){
            int4 a = ((const int4*)s_a)[c];
            int4 w = wr[c];
            acc=__dp4a(a.x,w.x,acc); acc=__dp4a(a.y,w.y,acc);
            acc=__dp4a(a.z,w.z,acc); acc=__dp4a(a.w,w.w,acc);
        }
        float y = ((float)acc - tn[2]) / sqrtf(tn[3] + 1e-4f) * tn[0] + tn[1];
        out[b*10 + tid] = y;
    }
}

// ---------------- host ----------------
extern "C" void kernel_launch(void* const* d_in, const int* in_sizes, int n_in,
                              void* d_out, int out_size)
{
    const float *x=0, *wc[6]={0,0,0,0,0,0}, *bnc[6]={0,0,0,0,0,0};
    const float *wf[3]={0,0,0}, *bnf[2]={0,0}, *tn=0;
    int n256=0, n512=0, n1024=0, n2048=0;
    for (int i=0;i<n_in;i++){
        const float* p = (const float*)d_in[i];
        switch (in_sizes[i]){
            case 3145728: x = p; break;
            case 1728:    wc[0]=p; break;
            case 36864:   wc[1]=p; break;
            case 73728:   wc[2]=p; break;
            case 147456:  wc[3]=p; break;
            case 294912:  wc[4]=p; break;
            case 589824:  wc[5]=p; break;
            case 131072:  wf[0]=p; break;
            case 262144:  wf[1]=p; break;
            case 5120:    wf[2]=p; break;
            case 256:     if(n256 <2) bnc[0+n256++ ]=p; break;
            case 512:     if(n512 <2) bnc[2+n512++ ]=p; break;
            case 1024:    if(n1024<2) bnc[4+n1024++]=p; break;
            case 2048:    if(n2048<2) bnf[n2048++  ]=p; break;
            case 4:       tn = p; break;
            default: break;
        }
    }

    int8_t *a0,*c0,*c1,*p1,*c2,*c3,*p3,*c4,*c5,*f0,*f1;
    int8_t *w0,*w1,*w2,*w3,*w4,*w5,*wf0d,*wf1d,*wf2d;
    float *bns,*bnm,*bnb,*fns,*fnm,*fnb;
    cudaGetSymbolAddress((void**)&a0, g_a0);  cudaGetSymbolAddress((void**)&c0, g_c0);
    cudaGetSymbolAddress((void**)&c1, g_c1);  cudaGetSymbolAddress((void**)&p1, g_p1);
    cudaGetSymbolAddress((void**)&c2, g_c2);  cudaGetSymbolAddress((void**)&c3, g_c3);
    cudaGetSymbolAddress((void**)&p3, g_p3);  cudaGetSymbolAddress((void**)&c4, g_c4);
    cudaGetSymbolAddress((void**)&c5, g_c5);  cudaGetSymbolAddress((void**)&f0, g_f0);
    cudaGetSymbolAddress((void**)&f1, g_f1);
    cudaGetSymbolAddress((void**)&w0, g_w0);  cudaGetSymbolAddress((void**)&w1, g_w1);
    cudaGetSymbolAddress((void**)&w2, g_w2);  cudaGetSymbolAddress((void**)&w3, g_w3);
    cudaGetSymbolAddress((void**)&w4, g_w4);  cudaGetSymbolAddress((void**)&w5, g_w5);
    cudaGetSymbolAddress((void**)&wf0d, g_wf0); cudaGetSymbolAddress((void**)&wf1d, g_wf1);
    cudaGetSymbolAddress((void**)&wf2d, g_wf2);
    cudaGetSymbolAddress((void**)&bns, g_bns); cudaGetSymbolAddress((void**)&bnm, g_bnm);
    cudaGetSymbolAddress((void**)&bnb, g_bnb);
    cudaGetSymbolAddress((void**)&fns, g_fns); cudaGetSymbolAddress((void**)&fnm, g_fnm);
    cudaGetSymbolAddress((void**)&fnb, g_fnb);

    const int T = 256;
    // launch 0
    k_inquant<<<(BSZ*1024+T-1)/T, T>>>(x, a0);
    // launch 1: all weights (1,543,424 elems)
    k_wprep_all<<<(1543424+T-1)/T, T>>>(wc[0],wc[1],wc[2],wc[3],wc[4],wc[5],
                                        wf[0],wf[1],wf[2]);
    // launch 2,3: bn
    k_bnprep_conv<<<6, 256>>>(bnc[0],bnc[1],bnc[2],bnc[3],bnc[4],bnc[5]);
    k_bnprep_fc<<<2, 512>>>(bnf[0], bnf[1]);

    // launch 4: conv0 (dp4a)
    {
        const int SM = 64*9*4 + 1*32*32*4;
        k_conv<4,64,64,32,32,1,true><<<dim3(1024,1), T, SM>>>(a0, w0, bns, bnm, bnb, c0);
    }
    // launch 5: conv1 (mma)  <- ncu -s 5 profiles this
    {
        const int SM = 1*900*80 + 64*592;        // 109,888
        cudaFuncSetAttribute(k_cmma<64,64,64,30,30,1>,
                             cudaFuncAttributeMaxDynamicSharedMemorySize, SM);
        k_cmma<64,64,64,30,30,1><<<dim3(1024,1), T, SM>>>(c0, w1, bns+256, bnm+256, bnb+256, c1);
    }
    k_pool<64,28,28><<<(BSZ*14*14*16+T-1)/T, T>>>(c1, p1);
    {   // conv2: 64->128, NIMG=2
        const int SM = 2*196*80 + 128*592;       // 107,136
        cudaFuncSetAttribute(k_cmma<64,128,128,14,14,2>,
                             cudaFuncAttributeMaxDynamicSharedMemorySize, SM);
        k_cmma<64,128,128,14,14,2><<<dim3(512,1), T, SM>>>(p1, w2, bns+512, bnm+512, bnb+512, c2);
    }
    {   // conv3: 128->128, NIMG=2
        const int SM = 2*144*144 + 128*1168;     // 190,976
        cudaFuncSetAttribute(k_cmma<128,128,128,12,12,2>,
                             cudaFuncAttributeMaxDynamicSharedMemorySize, SM);
        k_cmma<128,128,128,12,12,2><<<dim3(512,1), T, SM>>>(c2, w3, bns+768, bnm+768, bnb+768, c3);
    }
    k_pool<128,10,10><<<(BSZ*5*5*32+T-1)/T, T>>>(c3, p3);
    {   // conv4: 128->256 (mma), NIMG=8, OCT=128
        const int SM = 8*25*144 + 128*1168;      // 178,304
        cudaFuncSetAttribute(k_cmma<128,256,128,5,5,8>,
                             cudaFuncAttributeMaxDynamicSharedMemorySize, SM);
        k_cmma<128,256,128,5,5,8><<<dim3(128,2), T, SM>>>(p3, w4, bns+1024, bnm+1024, bnb+1024, c4);
    }
    // conv5 (1x1 spatial) == FC with FI=2304
    k_fc<2304,256,8><<<BSZ/8, T>>>(c4, w5, bns+1280, bnm+1280, bnb+1280, c5);
    // FC head
    k_fc<256,512,8><<<BSZ/8, T>>>(c5, wf0d, fns,     fnm,     fnb,     f0);
    k_fc<512,512,8><<<BSZ/8, T>>>(f0, wf1d, fns+512, fnm+512, fnb+512, f1);
    k_fc_last<<<BSZ, T>>>(f1, wf2d, tn, (float*)d_out);
}

// round 6
// speedup vs baseline: 3.0841x; 1.0730x over previous
#include <cuda_runtime.h>
#include <cstdint>

#define BSZ 1024

// ---------------- static device buffers ----------------
__device__ int8_t g_c0[BSZ*30*30*64];
__device__ int8_t g_c1[BSZ*28*28*64];
__device__ int8_t g_p1[BSZ*14*14*64];
__device__ int8_t g_c2[BSZ*12*12*128];
__device__ int8_t g_c3[BSZ*10*10*128];
__device__ int8_t g_p3[BSZ*5*5*128];
__device__ int8_t g_c4[BSZ*3*3*256];
__device__ int8_t g_c5[BSZ*256];
__device__ int8_t g_f0[BSZ*512];
__device__ int8_t g_f1[BSZ*512];

__device__ int8_t g_w0[64*36];        // dense [oc][9*4]  (dp4a conv0)
__device__ int8_t g_w1[64*592];       // padded [oc][576+16]  (cmma)
__device__ int8_t g_w2[128*592];
__device__ int8_t g_w3[128*1168];
__device__ int8_t g_w4[256*1168];
__device__ int8_t g_w5[256*2304];     // [oc][9][256] im2col order (gemm)
__device__ int8_t g_wf0[512*256];     // dense (gemm)
__device__ int8_t g_wf1[512*512];     // dense (gemm)
__device__ int8_t g_wf2[10*512];

__device__ float g_bns[6*256], g_bnm[6*256], g_bnb[6*256];
__device__ float g_fns[2*512], g_fnm[2*512], g_fnb[2*512];

// ---------------- helpers ----------------
__device__ __forceinline__ int8_t qtern(float y){
    float r = rintf(y);
    r = fminf(fmaxf(r, -1.f), 1.f);
    return (int8_t)r;
}

__device__ __forceinline__ void mma_s8(int* c, int a0,int a1,int a2,int a3,int b0,int b1){
    asm volatile(
        "mma.sync.aligned.m16n8k32.row.col.s32.s8.s8.s32 "
        "{%0,%1,%2,%3},{%4,%5,%6,%7},{%8,%9},{%0,%1,%2,%3};"
        : "+r"(c[0]),"+r"(c[1]),"+r"(c[2]),"+r"(c[3])
        : "r"(a0),"r"(a1),"r"(a2),"r"(a3),"r"(b0),"r"(b1));
}

__device__ __forceinline__ void ldsm_x4(uint32_t addr, int& r0,int& r1,int& r2,int& r3){
    asm volatile("ldmatrix.sync.aligned.m8n8.x4.shared.b16 {%0,%1,%2,%3}, [%4];"
        : "=r"(r0),"=r"(r1),"=r"(r2),"=r"(r3) : "r"(addr));
}
__device__ __forceinline__ void ldsm_x2(uint32_t addr, int& r0,int& r1){
    asm volatile("ldmatrix.sync.aligned.m8n8.x2.shared.b16 {%0,%1}, [%2];"
        : "=r"(r0),"=r"(r1) : "r"(addr));
}

__device__ __forceinline__ int8_t wq(float v){
    float r = rintf(v);
    r = fminf(fmaxf(r, -1.f), 1.f);
    return (int8_t)r;
}

// ---------------- merged prep kernels ----------------
__device__ __forceinline__ void wq_conv(const float* __restrict__ src, int8_t* dst,
                                        int CI, int CIP, int KP, int idx){
    int c  = idx % CIP;
    int k  = (idx / CIP) % 9;
    int oc = idx / (9*CIP);
    int8_t q = 0;
    if (c < CI) q = wq(src[(size_t)(oc*CI + c)*9 + k]);
    dst[(size_t)oc*KP + k*CIP + c] = q;
}

__global__ void k_wprep_all(const float* wc0,const float* wc1,const float* wc2,
                            const float* wc3,const float* wc4,const float* wc5,
                            const float* wf0,const float* wf1,const float* wf2){
    int idx = blockIdx.x*256 + threadIdx.x;
    if (idx < 2304)  { wq_conv(wc0, g_w0, 3,  4,  36,  idx); return; }  idx -= 2304;
    if (idx < 36864) { wq_conv(wc1, g_w1, 64, 64, 592, idx); return; }  idx -= 36864;
    if (idx < 73728) { wq_conv(wc2, g_w2, 64, 64, 592, idx); return; }  idx -= 73728;
    if (idx < 147456){ wq_conv(wc3, g_w3, 128,128,1168,idx); return; }  idx -= 147456;
    if (idx < 294912){ wq_conv(wc4, g_w4, 128,128,1168,idx); return; }  idx -= 294912;
    if (idx < 589824){ wq_conv(wc5, g_w5, 256,256,2304,idx); return; }  idx -= 589824;
    if (idx < 131072){ g_wf0[idx] = wq(wf0[idx]); return; }             idx -= 131072;
    if (idx < 262144){ g_wf1[idx] = wq(wf1[idx]); return; }             idx -= 262144;
    if (idx < 5120)  { g_wf2[idx] = wq(wf2[idx]); }
}

__global__ void k_bnprep_all(const float* b0,const float* b1,const float* b2,
                             const float* b3,const float* b4,const float* b5,
                             const float* f0,const float* f1){
    int seg = blockIdx.x, c = threadIdx.x;   // blockDim = 512
    if (seg < 6){
        const float* srcs[6] = {b0,b1,b2,b3,b4,b5};
        const int    chs [6] = {64,64,128,128,256,256};
        int C = chs[seg];
        if (c >= C) return;
        const float* p = srcs[seg];
        g_bns[seg*256+c] = p[c] / sqrtf(p[3*C+c] + 1e-4f);
        g_bnm[seg*256+c] = p[2*C+c];
        g_bnb[seg*256+c] = p[C+c];
    } else {
        int k = seg - 6;
        const float* p = k ? f1 : f0;
        g_fns[k*512+c] = p[c] / sqrtf(p[1536+c] + 1e-4f);
        g_fnm[k*512+c] = p[1024+c];
        g_fnb[k*512+c] = p[512+c];
    }
}

// ---------------- conv0: fused inquant + dp4a conv ----------------
__global__ void __launch_bounds__(256) k_conv0(
    const float* __restrict__ x, const int8_t* __restrict__ wt,
    const float* __restrict__ bs, const float* __restrict__ bm, const float* __restrict__ bb,
    int8_t* __restrict__ out)
{
    __shared__ int8_t s_w[64*36];
    __shared__ int    s_in[1024];           // char4 per pixel
    const int tid = threadIdx.x;
    const int img = blockIdx.x;

    {
        const int4* src = (const int4*)wt;
        int4* dst = (int4*)s_w;
        for (int i = tid; i < 144; i += 256) dst[i] = src[i];
    }
    {
        const float* xb = x + (size_t)img*3072;
        for (int i = tid; i < 1024; i += 256){
            char4 r; float v;
            v = rintf(xb[i]     *128.f); v = fminf(fmaxf(v,-128.f),127.f); r.x = (signed char)v;
            v = rintf(xb[1024+i]*128.f); v = fminf(fmaxf(v,-128.f),127.f); r.y = (signed char)v;
            v = rintf(xb[2048+i]*128.f); v = fminf(fmaxf(v,-128.f),127.f); r.z = (signed char)v;
            r.w = 0;
            s_in[i] = *(int*)&r;
        }
    }
    __syncthreads();

    constexpr int TOT = 900*4;              // NPIX * NOCG
    for (int t = tid; t < TOT; t += 256){
        int pix = t % 900;
        int ocg = t / 900;
        int oy = pix / 30, ox = pix % 30;
        int acc[16];
        #pragma unroll
        for (int j=0;j<16;j++) acc[j]=0;
        const int8_t* wb_ = s_w + ocg*16*36;

        #pragma unroll
        for (int ky=0; ky<3; ky++){
            #pragma unroll
            for (int kx=0; kx<3; kx++){
                const int a  = s_in[(oy+ky)*32 + ox + kx];
                const int kk = ky*3 + kx;
                #pragma unroll
                for (int j=0;j<16;j++){
                    int w = *(const int*)(wb_ + (j*9 + kk)*4);
                    acc[j] = __dp4a(a, w, acc[j]);
                }
            }
        }
        union { int8_t b[16]; int4 v; } q;
        #pragma unroll
        for (int j=0;j<16;j++){
            int oc = ocg*16 + j;
            float y = ((float)acc[j]*(1.0f/128.0f) - bm[oc]) * bs[oc] + bb[oc];
            q.b[j] = qtern(y);
        }
        *(int4*)(out + ((size_t)img*900 + pix)*64 + ocg*16) = q.v;
    }
}

// ---------------- implicit-GEMM conv via ldmatrix + mma.sync ----------------
template<int CIN,int COUT,int OCT,int HIN,int WIN,int NIMG>
__global__ void __launch_bounds__(256) k_cmma(
    const int8_t* __restrict__ in, const int8_t* __restrict__ wt,
    const float* __restrict__ bs, const float* __restrict__ bm, const float* __restrict__ bb,
    int8_t* __restrict__ out)
{
    constexpr int HOUT = HIN-2, WOUT = WIN-2;
    constexpr int NPIX = HOUT*WOUT, INPIX = HIN*WIN;
    constexpr int K  = 9*CIN, KP = K+16, SA = CIN+16;
    constexpr int CH = K/32;
    constexpr int CPT = CIN/32;
    constexpr int NT = OCT/32;
    constexpr int AW = NIMG*INPIX*SA;
    constexpr int NROWS = NIMG*NPIX;
    constexpr int MT = (NROWS + 63)/64;

    extern __shared__ int8_t smem[];
    int8_t* s_a = smem;
    int8_t* s_w = smem + AW;

    const int tid  = threadIdx.x;
    const int img0 = blockIdx.x * NIMG;
    const int ocb  = blockIdx.y * OCT;
    const int lane = tid & 31;
    const int warp = tid >> 5;
    const int wm   = warp & 1;
    const int wn   = warp >> 1;
    const int ocw  = wn * (OCT/4);

    {
        constexpr int RV = CIN/16;
        const int4* src = (const int4*)(in + (size_t)img0*INPIX*CIN);
        #pragma unroll 4
        for (int i = tid; i < NIMG*INPIX*RV; i += 256){
            int row = i / RV, j = i % RV;
            ((int4*)s_a)[row*(SA/16) + j] = src[i];
        }
    }
    {
        const int4* src = (const int4*)(wt + (size_t)ocb*KP);
        int4* dst = (int4*)s_w;
        #pragma unroll 4
        for (int i = tid; i < OCT*KP/16; i += 256) dst[i] = src[i];
    }
    __syncthreads();

    const uint32_t s_a32 = (uint32_t)__cvta_generic_to_shared(s_a);
    const uint32_t s_w32 = (uint32_t)__cvta_generic_to_shared(s_w);

    uint32_t baddr[NT];
    #pragma unroll
    for (int nt=0; nt<NT; nt++)
        baddr[nt] = s_w32 + (uint32_t)((ocw + nt*8 + (lane&7))*KP + ((lane>>3)&1)*16);

    float hs0[NT],hs1[NT],hm0[NT],hm1[NT],hb0[NT],hb1[NT];
    #pragma unroll
    for (int nt=0; nt<NT; nt++){
        int col = ocb + ocw + nt*8 + (lane&3)*2;
        hs0[nt]=bs[col];   hm0[nt]=bm[col];   hb0[nt]=bb[col];
        hs1[nt]=bs[col+1]; hm1[nt]=bm[col+1]; hb1[nt]=bb[col+1];
    }

    const int laneR = lane & 15;
    const int laneC = (lane >> 4) * 16;

    for (int mt = 0; mt < MT; mt++){
        const int rbase = mt*64 + wm*32;

        uint32_t aA[2];
        #pragma unroll
        for (int t=0; t<2; t++){
            int r = rbase + 16*t + laneR;
            if (r >= NROWS) r = 0;
            int im  = r / NPIX;
            int pix = r - im*NPIX;
            int py  = pix / WOUT;
            int px  = pix - py*WOUT;
            aA[t] = s_a32 + (uint32_t)((im*INPIX + py*WIN + px)*SA + laneC);
        }

        int acc[2][NT][4];
        #pragma unroll
        for (int t=0;t<2;t++)
            #pragma unroll
            for (int nt=0;nt<NT;nt++){ acc[t][nt][0]=acc[t][nt][1]=acc[t][nt][2]=acc[t][nt][3]=0; }

        #pragma unroll
        for (int ch = 0; ch < CH; ch++){
            const int kk = ch / CPT;
            const int cb = (ch % CPT)*32;
            const int aoff = ((kk/3)*WIN + (kk%3))*SA + cb;
            int a0,a1,a2,a3,a4,a5,a6,a7;
            ldsm_x4(aA[0]+aoff, a0,a1,a2,a3);
            ldsm_x4(aA[1]+aoff, a4,a5,a6,a7);
            #pragma unroll
            for (int nt=0; nt<NT; nt++){
                int b0,b1;
                ldsm_x2(baddr[nt] + ch*32, b0,b1);
                mma_s8(acc[0][nt], a0,a1,a2,a3, b0,b1);
                mma_s8(acc[1][nt], a4,a5,a6,a7, b0,b1);
            }
        }

        #pragma unroll
        for (int t=0; t<2; t++){
            const int pa = rbase + 16*t + (lane>>2);
            const int pb = pa + 8;
            int ia = pa / NPIX, xa = pa - ia*NPIX;
            int ib = pb / NPIX, xb = pb - ib*NPIX;
            int8_t* oa = out + ((size_t)(img0+ia)*NPIX + xa)*COUT + ocb + ocw + (lane&3)*2;
            int8_t* ob = out + ((size_t)(img0+ib)*NPIX + xb)*COUT + ocb + ocw + (lane&3)*2;
            #pragma unroll
            for (int nt=0; nt<NT; nt++){
                if (pa < NROWS){
                    char2 o;
                    o.x = qtern(((float)acc[t][nt][0] - hm0[nt])*hs0[nt] + hb0[nt]);
                    o.y = qtern(((float)acc[t][nt][1] - hm1[nt])*hs1[nt] + hb1[nt]);
                    *(char2*)(oa + nt*8) = o;
                }
                if (pb < NROWS){
                    char2 o;
                    o.x = qtern(((float)acc[t][nt][2] - hm0[nt])*hs0[nt] + hb0[nt]);
                    o.y = qtern(((float)acc[t][nt][3] - hm1[nt])*hs1[nt] + hb1[nt]);
                    *(char2*)(ob + nt*8) = o;
                }
            }
        }
    }
}

// ---------------- GEMM via ldmatrix + mma.sync (conv5/fc0/fc1) ----------------
// CTA tile 64(M) x 128(N); K streamed in 256-byte chunks through smem.
template<int K,int N>
__global__ void __launch_bounds__(256) k_gemm(
    const int8_t* __restrict__ in, const int8_t* __restrict__ wt,
    const float* __restrict__ bs, const float* __restrict__ bm, const float* __restrict__ bb,
    int8_t* __restrict__ out)
{
    constexpr int KC = 256, SK = KC+16;
    extern __shared__ int8_t smem[];
    int8_t* s_a = smem;             // 64*SK
    int8_t* s_b = smem + 64*SK;     // 128*SK

    const int tid  = threadIdx.x;
    const int lane = tid & 31;
    const int warp = tid >> 5;
    const int wm   = warp & 1;
    const int wn   = warp >> 1;
    const int m0   = blockIdx.x * 64;
    const int n0   = blockIdx.y * 128;

    const uint32_t a32 = (uint32_t)__cvta_generic_to_shared(s_a);
    const uint32_t b32 = (uint32_t)__cvta_generic_to_shared(s_b);
    const int laneR = lane & 15;
    const int laneC = (lane >> 4) * 16;

    int acc[2][4][4];
    #pragma unroll
    for (int t=0;t<2;t++)
        #pragma unroll
        for (int nt=0;nt<4;nt++){ acc[t][nt][0]=acc[t][nt][1]=acc[t][nt][2]=acc[t][nt][3]=0; }

    for (int kc = 0; kc < K; kc += KC){
        if (kc) __syncthreads();
        for (int i = tid; i < 64*16; i += 256){
            int row = i >> 4, j = i & 15;
            ((int4*)s_a)[row*17 + j] = *(const int4*)(in + (size_t)(m0+row)*K + kc + j*16);
        }
        for (int i = tid; i < 128*16; i += 256){
            int row = i >> 4, j = i & 15;
            ((int4*)s_b)[row*17 + j] = *(const int4*)(wt + (size_t)(n0+row)*K + kc + j*16);
        }
        __syncthreads();

        #pragma unroll
        for (int ch = 0; ch < KC/32; ch++){
            int a0,a1,a2,a3,a4,a5,a6,a7;
            ldsm_x4(a32 + (wm*32 + laneR)*SK + laneC + ch*32,      a0,a1,a2,a3);
            ldsm_x4(a32 + (wm*32 + 16 + laneR)*SK + laneC + ch*32, a4,a5,a6,a7);
            #pragma unroll
            for (int nt=0; nt<4; nt++){
                int b0,b1;
                ldsm_x2(b32 + (wn*32 + nt*8 + (lane&7))*SK + ((lane>>3)&1)*16 + ch*32, b0,b1);
                mma_s8(acc[0][nt], a0,a1,a2,a3, b0,b1);
                mma_s8(acc[1][nt], a4,a5,a6,a7, b0,b1);
            }
        }
    }

    #pragma unroll
    for (int nt=0; nt<4; nt++){
        const int col = n0 + wn*32 + nt*8 + (lane&3)*2;
        const float s0 = bs[col],   m_ = bm[col],   b0_ = bb[col];
        const float s1 = bs[col+1], m1 = bm[col+1], b1_ = bb[col+1];
        #pragma unroll
        for (int t=0; t<2; t++){
            const int ra = m0 + wm*32 + 16*t + (lane>>2);
            char2 o;
            o.x = qtern(((float)acc[t][nt][0] - m_)*s0 + b0_);
            o.y = qtern(((float)acc[t][nt][1] - m1)*s1 + b1_);
            *(char2*)(out + (size_t)ra*N + col) = o;
            o.x = qtern(((float)acc[t][nt][2] - m_)*s0 + b0_);
            o.y = qtern(((float)acc[t][nt][3] - m1)*s1 + b1_);
            *(char2*)(out + (size_t)(ra+8)*N + col) = o;
        }
    }
}

// ---------------- pool ----------------
template<int C,int HIN,int WIN>
__global__ void k_pool(const int8_t* __restrict__ in, int8_t* __restrict__ out){
    constexpr int HO=HIN/2, WO=WIN/2, C4=C/4;
    constexpr int TOT = BSZ*HO*WO*C4;
    int idx = blockIdx.x*256 + threadIdx.x;
    if (idx >= TOT) return;
    int c4 = idx % C4;
    int rr = idx / C4;
    int ox = rr % WO; rr /= WO;
    int oy = rr % HO;
    int b  = rr / HO;
    const int8_t* base = in + ((size_t)(b*HIN + 2*oy)*WIN + 2*ox)*C + c4*4;
    char4 a0 = *(const char4*)base;
    char4 a1 = *(const char4*)(base + C);
    char4 a2 = *(const char4*)(base + (size_t)WIN*C);
    char4 a3 = *(const char4*)(base + (size_t)WIN*C + C);
    char4 o;
    o.x = qtern((float)(a0.x+a1.x+a2.x+a3.x) * 0.25f);
    o.y = qtern((float)(a0.y+a1.y+a2.y+a3.y) * 0.25f);
    o.z = qtern((float)(a0.z+a1.z+a2.z+a3.z) * 0.25f);
    o.w = qtern((float)(a0.w+a1.w+a2.w+a3.w) * 0.25f);
    ((char4*)out)[idx] = o;
}

// ---------------- last FC + TensorNorm ----------------
__global__ void k_fc_last(const int8_t* __restrict__ in, const int8_t* __restrict__ wt,
                          const float* __restrict__ tn, float* __restrict__ out){
    __shared__ int8_t s_a[512];
    int b = blockIdx.x, tid = threadIdx.x;
    for (int i = tid; i < 32; i += 256)
        ((int4*)s_a)[i] = ((const int4*)(in + (size_t)b*512))[i];
    __syncthreads();
    if (tid < 10){
        const int4* wr = (const int4*)(wt + (size_t)tid*512);
        int acc = 0;
        #pragma unroll 8
        for (int c=0;c<32;c++){
            int4 a = ((const int4*)s_a)[c];
            int4 w = wr[c];
            acc=__dp4a(a.x,w.x,acc); acc=__dp4a(a.y,w.y,acc);
            acc=__dp4a(a.z,w.z,acc); acc=__dp4a(a.w,w.w,acc);
        }
        float y = ((float)acc - tn[2]) / sqrtf(tn[3] + 1e-4f) * tn[0] + tn[1];
        out[b*10 + tid] = y;
    }
}

// ---------------- host ----------------
extern "C" void kernel_launch(void* const* d_in, const int* in_sizes, int n_in,
                              void* d_out, int out_size)
{
    const float *x=0, *wc[6]={0,0,0,0,0,0}, *bnc[6]={0,0,0,0,0,0};
    const float *wf[3]={0,0,0}, *bnf[2]={0,0}, *tn=0;
    int n256=0, n512=0, n1024=0, n2048=0;
    for (int i=0;i<n_in;i++){
        const float* p = (const float*)d_in[i];
        switch (in_sizes[i]){
            case 3145728: x = p; break;
            case 1728:    wc[0]=p; break;
            case 36864:   wc[1]=p; break;
            case 73728:   wc[2]=p; break;
            case 147456:  wc[3]=p; break;
            case 294912:  wc[4]=p; break;
            case 589824:  wc[5]=p; break;
            case 131072:  wf[0]=p; break;
            case 262144:  wf[1]=p; break;
            case 5120:    wf[2]=p; break;
            case 256:     if(n256 <2) bnc[0+n256++ ]=p; break;
            case 512:     if(n512 <2) bnc[2+n512++ ]=p; break;
            case 1024:    if(n1024<2) bnc[4+n1024++]=p; break;
            case 2048:    if(n2048<2) bnf[n2048++  ]=p; break;
            case 4:       tn = p; break;
            default: break;
        }
    }

    int8_t *c0,*c1,*p1,*c2,*c3,*p3,*c4,*c5,*f0,*f1;
    int8_t *w0,*w1,*w2,*w3,*w4,*w5,*wf0d,*wf1d,*wf2d;
    float *bns,*bnm,*bnb,*fns,*fnm,*fnb;
    cudaGetSymbolAddress((void**)&c0, g_c0);
    cudaGetSymbolAddress((void**)&c1, g_c1);  cudaGetSymbolAddress((void**)&p1, g_p1);
    cudaGetSymbolAddress((void**)&c2, g_c2);  cudaGetSymbolAddress((void**)&c3, g_c3);
    cudaGetSymbolAddress((void**)&p3, g_p3);  cudaGetSymbolAddress((void**)&c4, g_c4);
    cudaGetSymbolAddress((void**)&c5, g_c5);  cudaGetSymbolAddress((void**)&f0, g_f0);
    cudaGetSymbolAddress((void**)&f1, g_f1);
    cudaGetSymbolAddress((void**)&w0, g_w0);  cudaGetSymbolAddress((void**)&w1, g_w1);
    cudaGetSymbolAddress((void**)&w2, g_w2);  cudaGetSymbolAddress((void**)&w3, g_w3);
    cudaGetSymbolAddress((void**)&w4, g_w4);  cudaGetSymbolAddress((void**)&w5, g_w5);
    cudaGetSymbolAddress((void**)&wf0d, g_wf0); cudaGetSymbolAddress((void**)&wf1d, g_wf1);
    cudaGetSymbolAddress((void**)&wf2d, g_wf2);
    cudaGetSymbolAddress((void**)&bns, g_bns); cudaGetSymbolAddress((void**)&bnm, g_bnm);
    cudaGetSymbolAddress((void**)&bnb, g_bnb);
    cudaGetSymbolAddress((void**)&fns, g_fns); cudaGetSymbolAddress((void**)&fnm, g_fnm);
    cudaGetSymbolAddress((void**)&fnb, g_fnb);

    const int T = 256;
    const int GSM = 64*272 + 128*272;            // 52,224 gemm smem

    // launch 0: all weights
    k_wprep_all<<<(1543424+T-1)/T, T>>>(wc[0],wc[1],wc[2],wc[3],wc[4],wc[5],
                                        wf[0],wf[1],wf[2]);
    // launch 1: all bn
    k_bnprep_all<<<8, 512>>>(bnc[0],bnc[1],bnc[2],bnc[3],bnc[4],bnc[5], bnf[0],bnf[1]);
    // launch 2: conv0 (fused inquant)
    k_conv0<<<1024, T>>>(x, w0, bns, bnm, bnb, c0);
    // launch 3: conv1
    {
        const int SM = 1*900*80 + 64*592;        // 109,888
        cudaFuncSetAttribute(k_cmma<64,64,64,30,30,1>,
                             cudaFuncAttributeMaxDynamicSharedMemorySize, SM);
        k_cmma<64,64,64,30,30,1><<<dim3(1024,1), T, SM>>>(c0, w1, bns+256, bnm+256, bnb+256, c1);
    }
    // launch 4: pool1
    k_pool<64,28,28><<<(BSZ*14*14*16+T-1)/T, T>>>(c1, p1);
    // launch 5: conv2
    {
        const int SM = 2*196*80 + 128*592;       // 107,136
        cudaFuncSetAttribute(k_cmma<64,128,128,14,14,2>,
                             cudaFuncAttributeMaxDynamicSharedMemorySize, SM);
        k_cmma<64,128,128,14,14,2><<<dim3(512,1), T, SM>>>(p1, w2, bns+512, bnm+512, bnb+512, c2);
    }
    // launch 6: conv3
    {
        const int SM = 2*144*144 + 128*1168;     // 190,976
        cudaFuncSetAttribute(k_cmma<128,128,128,12,12,2>,
                             cudaFuncAttributeMaxDynamicSharedMemorySize, SM);
        k_cmma<128,128,128,12,12,2><<<dim3(512,1), T, SM>>>(c2, w3, bns+768, bnm+768, bnb+768, c3);
    }
    // launch 7: pool3
    k_pool<128,10,10><<<(BSZ*5*5*32+T-1)/T, T>>>(c3, p3);
    // launch 8: conv4
    {
        const int SM = 8*25*144 + 128*1168;      // 178,304
        cudaFuncSetAttribute(k_cmma<128,256,128,5,5,8>,
                             cudaFuncAttributeMaxDynamicSharedMemorySize, SM);
        k_cmma<128,256,128,5,5,8><<<dim3(128,2), T, SM>>>(p3, w4, bns+1024, bnm+1024, bnb+1024, c4);
    }
    // launch 9: conv5 as GEMM (M=1024, N=256, K=2304)
    cudaFuncSetAttribute(k_gemm<2304,256>, cudaFuncAttributeMaxDynamicSharedMemorySize, GSM);
    k_gemm<2304,256><<<dim3(16,2), T, GSM>>>(c4, w5, bns+1280, bnm+1280, bnb+1280, c5);
    // launch 10: fc0 (K=256, N=512)
    cudaFuncSetAttribute(k_gemm<256,512>, cudaFuncAttributeMaxDynamicSharedMemorySize, GSM);
    k_gemm<256,512><<<dim3(16,4), T, GSM>>>(c5, wf0d, fns, fnm, fnb, f0);
    // launch 11: fc1 (K=512, N=512)
    cudaFuncSetAttribute(k_gemm<512,512>, cudaFuncAttributeMaxDynamicSharedMemorySize, GSM);
    k_gemm<512,512><<<dim3(16,4), T, GSM>>>(f0, wf1d, fns+512, fnm+512, fnb+512, f1);
    // launch 12: fc2 + TensorNorm
    k_fc_last<<<BSZ, T>>>(f1, wf2d, tn, (float*)d_out);
}

// round 7
// speedup vs baseline: 3.2317x; 1.0478x over previous
#include <cuda_runtime.h>
#include <cstdint>

#define BSZ 1024

// ---------------- static device buffers ----------------
__device__ int8_t g_c0[BSZ*30*30*64];
__device__ int8_t g_c1[BSZ*28*28*64];
__device__ int8_t g_p1[BSZ*14*14*64];
__device__ int8_t g_c2[BSZ*12*12*128];
__device__ int8_t g_c3[BSZ*10*10*128];
__device__ int8_t g_p3[BSZ*5*5*128];
__device__ int8_t g_c4[BSZ*3*3*256];
__device__ int8_t g_c5[BSZ*256];
__device__ int8_t g_f0[BSZ*512];
__device__ int8_t g_f1[BSZ*512];

__device__ int8_t g_w0[64*36];
__device__ int8_t g_w1[64*592];
__device__ int8_t g_w2[128*592];
__device__ int8_t g_w3[128*1168];
__device__ int8_t g_w4[256*1168];
__device__ int8_t g_w5[256*2304];     // [oc][9][256] im2col order (gemm)
__device__ int8_t g_wf0[512*256];
__device__ int8_t g_wf1[512*512];
__device__ int8_t g_wf2[10*512];

__device__ float g_bns[6*256], g_bnm[6*256], g_bnb[6*256];
__device__ float g_fns[2*512], g_fnm[2*512], g_fnb[2*512];

// ---------------- helpers ----------------
__device__ __forceinline__ int8_t qtern(float y){
    float r = rintf(y);
    r = fminf(fmaxf(r, -1.f), 1.f);
    return (int8_t)r;
}

__device__ __forceinline__ void mma_s8(int* c, int a0,int a1,int a2,int a3,int b0,int b1){
    asm volatile(
        "mma.sync.aligned.m16n8k32.row.col.s32.s8.s8.s32 "
        "{%0,%1,%2,%3},{%4,%5,%6,%7},{%8,%9},{%0,%1,%2,%3};"
        : "+r"(c[0]),"+r"(c[1]),"+r"(c[2]),"+r"(c[3])
        : "r"(a0),"r"(a1),"r"(a2),"r"(a3),"r"(b0),"r"(b1));
}

__device__ __forceinline__ void ldsm_x4(uint32_t addr, int& r0,int& r1,int& r2,int& r3){
    asm volatile("ldmatrix.sync.aligned.m8n8.x4.shared.b16 {%0,%1,%2,%3}, [%4];"
        : "=r"(r0),"=r"(r1),"=r"(r2),"=r"(r3) : "r"(addr));
}

__device__ __forceinline__ int8_t wq(float v){
    float r = rintf(v);
    r = fminf(fmaxf(r, -1.f), 1.f);
    return (int8_t)r;
}

// ---------------- merged prep kernels ----------------
__device__ __forceinline__ void wq_conv(const float* __restrict__ src, int8_t* dst,
                                        int CI, int CIP, int KP, int idx){
    int c  = idx % CIP;
    int k  = (idx / CIP) % 9;
    int oc = idx / (9*CIP);
    int8_t q = 0;
    if (c < CI) q = wq(src[(size_t)(oc*CI + c)*9 + k]);
    dst[(size_t)oc*KP + k*CIP + c] = q;
}

__global__ void k_wprep_all(const float* wc0,const float* wc1,const float* wc2,
                            const float* wc3,const float* wc4,const float* wc5,
                            const float* wf0,const float* wf1,const float* wf2){
    int idx = blockIdx.x*256 + threadIdx.x;
    if (idx < 2304)  { wq_conv(wc0, g_w0, 3,  4,  36,  idx); return; }  idx -= 2304;
    if (idx < 36864) { wq_conv(wc1, g_w1, 64, 64, 592, idx); return; }  idx -= 36864;
    if (idx < 73728) { wq_conv(wc2, g_w2, 64, 64, 592, idx); return; }  idx -= 73728;
    if (idx < 147456){ wq_conv(wc3, g_w3, 128,128,1168,idx); return; }  idx -= 147456;
    if (idx < 294912){ wq_conv(wc4, g_w4, 128,128,1168,idx); return; }  idx -= 294912;
    if (idx < 589824){ wq_conv(wc5, g_w5, 256,256,2304,idx); return; }  idx -= 589824;
    if (idx < 131072){ g_wf0[idx] = wq(wf0[idx]); return; }             idx -= 131072;
    if (idx < 262144){ g_wf1[idx] = wq(wf1[idx]); return; }             idx -= 262144;
    if (idx < 5120)  { g_wf2[idx] = wq(wf2[idx]); }
}

__global__ void k_bnprep_all(const float* b0,const float* b1,const float* b2,
                             const float* b3,const float* b4,const float* b5,
                             const float* f0,const float* f1){
    int seg = blockIdx.x, c = threadIdx.x;   // blockDim = 512
    if (seg < 6){
        const float* srcs[6] = {b0,b1,b2,b3,b4,b5};
        const int    chs [6] = {64,64,128,128,256,256};
        int C = chs[seg];
        if (c >= C) return;
        const float* p = srcs[seg];
        g_bns[seg*256+c] = p[c] / sqrtf(p[3*C+c] + 1e-4f);
        g_bnm[seg*256+c] = p[2*C+c];
        g_bnb[seg*256+c] = p[C+c];
    } else {
        int k = seg - 6;
        const float* p = k ? f1 : f0;
        g_fns[k*512+c] = p[c] / sqrtf(p[1536+c] + 1e-4f);
        g_fnm[k*512+c] = p[1024+c];
        g_fnb[k*512+c] = p[512+c];
    }
}

// ---------------- conv0: fused inquant + dp4a conv ----------------
__global__ void __launch_bounds__(256) k_conv0(
    const float* __restrict__ x, const int8_t* __restrict__ wt,
    const float* __restrict__ bs, const float* __restrict__ bm, const float* __restrict__ bb,
    int8_t* __restrict__ out)
{
    __shared__ int8_t s_w[64*36];
    __shared__ int    s_in[1024];
    const int tid = threadIdx.x;
    const int img = blockIdx.x;

    {
        const int4* src = (const int4*)wt;
        int4* dst = (int4*)s_w;
        for (int i = tid; i < 144; i += 256) dst[i] = src[i];
    }
    {
        const float* xb = x + (size_t)img*3072;
        for (int i = tid; i < 1024; i += 256){
            char4 r; float v;
            v = rintf(xb[i]     *128.f); v = fminf(fmaxf(v,-128.f),127.f); r.x = (signed char)v;
            v = rintf(xb[1024+i]*128.f); v = fminf(fmaxf(v,-128.f),127.f); r.y = (signed char)v;
            v = rintf(xb[2048+i]*128.f); v = fminf(fmaxf(v,-128.f),127.f); r.z = (signed char)v;
            r.w = 0;
            s_in[i] = *(int*)&r;
        }
    }
    __syncthreads();

    constexpr int TOT = 900*4;
    for (int t = tid; t < TOT; t += 256){
        int pix = t % 900;
        int ocg = t / 900;
        int oy = pix / 30, ox = pix % 30;
        int acc[16];
        #pragma unroll
        for (int j=0;j<16;j++) acc[j]=0;
        const int8_t* wb_ = s_w + ocg*16*36;

        #pragma unroll
        for (int ky=0; ky<3; ky++){
            #pragma unroll
            for (int kx=0; kx<3; kx++){
                const int a  = s_in[(oy+ky)*32 + ox + kx];
                const int kk = ky*3 + kx;
                #pragma unroll
                for (int j=0;j<16;j++){
                    int w = *(const int*)(wb_ + (j*9 + kk)*4);
                    acc[j] = __dp4a(a, w, acc[j]);
                }
            }
        }
        union { int8_t b[16]; int4 v; } q;
        #pragma unroll
        for (int j=0;j<16;j++){
            int oc = ocg*16 + j;
            float y = ((float)acc[j]*(1.0f/128.0f) - bm[oc]) * bs[oc] + bb[oc];
            q.b[j] = qtern(y);
        }
        *(int4*)(out + ((size_t)img*900 + pix)*64 + ocg*16) = q.v;
    }
}

// ---------------- implicit-GEMM conv via ldmatrix + mma.sync ----------------
// 8 warps = 4 m-warps (32 rows) x 2 n-warps (32 oc). CTA tile 128 x 64.
// Per chunk per warp: 2 A ldsm.x4 + 2 B ldsm.x4 -> 8 mma (2 wavefronts/mma).
template<int CIN,int COUT,int OCT,int HIN,int WIN,int NIMG>
__global__ void __launch_bounds__(256) k_cmma(
    const int8_t* __restrict__ in, const int8_t* __restrict__ wt,
    const float* __restrict__ bs, const float* __restrict__ bm, const float* __restrict__ bb,
    int8_t* __restrict__ out)
{
    constexpr int HOUT = HIN-2, WOUT = WIN-2;
    constexpr int NPIX = HOUT*WOUT, INPIX = HIN*WIN;
    constexpr int K  = 9*CIN, KP = K+16, SA = CIN+16;
    constexpr int CH = K/32;
    constexpr int CPT = CIN/32;
    constexpr int NT = OCT/16;          // 4 n8 tiles per warp (OCT=64)
    constexpr int NP = NT/2;            // B ldsm.x4 pairs
    constexpr int AW = NIMG*INPIX*SA;
    constexpr int NROWS = NIMG*NPIX;
    constexpr int MT = (NROWS + 127)/128;

    extern __shared__ int8_t smem[];
    int8_t* s_a = smem;
    int8_t* s_w = smem + AW;

    const int tid  = threadIdx.x;
    const int img0 = blockIdx.x * NIMG;
    const int ocb  = blockIdx.y * OCT;
    const int lane = tid & 31;
    const int warp = tid >> 5;
    const int wm   = warp & 3;          // 4 m-warps
    const int wn   = warp >> 2;         // 2 n-warps
    const int ocw  = wn * (OCT/2);      // 32 oc per warp

    {
        constexpr int RV = CIN/16;
        const int4* src = (const int4*)(in + (size_t)img0*INPIX*CIN);
        #pragma unroll 4
        for (int i = tid; i < NIMG*INPIX*RV; i += 256){
            int row = i / RV, j = i % RV;
            ((int4*)s_a)[row*(SA/16) + j] = src[i];
        }
    }
    {
        const int4* src = (const int4*)(wt + (size_t)ocb*KP);
        int4* dst = (int4*)s_w;
        #pragma unroll 4
        for (int i = tid; i < OCT*KP/16; i += 256) dst[i] = src[i];
    }
    __syncthreads();

    const uint32_t s_a32 = (uint32_t)__cvta_generic_to_shared(s_a);
    const uint32_t s_w32 = (uint32_t)__cvta_generic_to_shared(s_w);

    // B x4 addresses: lanes 0-15 -> oc rows p*16+(lane&7), lanes 16-31 -> +8
    uint32_t baddr[NP];
    #pragma unroll
    for (int p=0; p<NP; p++)
        baddr[p] = s_w32 + (uint32_t)((ocw + p*16 + ((lane>>4)<<3) + (lane&7))*KP
                                      + ((lane>>3)&1)*16);

    // hoisted BN params
    float hs0[NT],hs1[NT],hm0[NT],hm1[NT],hb0[NT],hb1[NT];
    #pragma unroll
    for (int nt=0; nt<NT; nt++){
        int col = ocb + ocw + nt*8 + (lane&3)*2;
        hs0[nt]=bs[col];   hm0[nt]=bm[col];   hb0[nt]=bb[col];
        hs1[nt]=bs[col+1]; hm1[nt]=bm[col+1]; hb1[nt]=bb[col+1];
    }

    const int laneR = lane & 15;
    const int laneC = (lane >> 4) * 16;

    for (int mt = 0; mt < MT; mt++){
        const int rbase = mt*128 + wm*32;

        uint32_t aA[2];
        #pragma unroll
        for (int t=0; t<2; t++){
            int r = rbase + 16*t + laneR;
            if (r >= NROWS) r = 0;
            int im  = r / NPIX;
            int pix = r - im*NPIX;
            int py  = pix / WOUT;
            int px  = pix - py*WOUT;
            aA[t] = s_a32 + (uint32_t)((im*INPIX + py*WIN + px)*SA + laneC);
        }

        int acc[2][NT][4];
        #pragma unroll
        for (int t=0;t<2;t++)
            #pragma unroll
            for (int nt=0;nt<NT;nt++){ acc[t][nt][0]=acc[t][nt][1]=acc[t][nt][2]=acc[t][nt][3]=0; }

        #pragma unroll
        for (int ch = 0; ch < CH; ch++){
            const int kk = ch / CPT;
            const int cb = (ch % CPT)*32;
            const int aoff = ((kk/3)*WIN + (kk%3))*SA + cb;
            int a0,a1,a2,a3,a4,a5,a6,a7;
            ldsm_x4(aA[0]+aoff, a0,a1,a2,a3);
            ldsm_x4(aA[1]+aoff, a4,a5,a6,a7);
            int b[NT][2];
            #pragma unroll
            for (int p=0; p<NP; p++)
                ldsm_x4(baddr[p] + ch*32, b[2*p][0], b[2*p][1], b[2*p+1][0], b[2*p+1][1]);
            #pragma unroll
            for (int nt=0; nt<NT; nt++){
                mma_s8(acc[0][nt], a0,a1,a2,a3, b[nt][0], b[nt][1]);
                mma_s8(acc[1][nt], a4,a5,a6,a7, b[nt][0], b[nt][1]);
            }
        }

        #pragma unroll
        for (int t=0; t<2; t++){
            const int pa = rbase + 16*t + (lane>>2);
            const int pb = pa + 8;
            int ia = pa / NPIX, xa = pa - ia*NPIX;
            int ib = pb / NPIX, xb = pb - ib*NPIX;
            int8_t* oa = out + ((size_t)(img0+ia)*NPIX + xa)*COUT + ocb + ocw + (lane&3)*2;
            int8_t* ob = out + ((size_t)(img0+ib)*NPIX + xb)*COUT + ocb + ocw + (lane&3)*2;
            #pragma unroll
            for (int nt=0; nt<NT; nt++){
                if (pa < NROWS){
                    char2 o;
                    o.x = qtern(((float)acc[t][nt][0] - hm0[nt])*hs0[nt] + hb0[nt]);
                    o.y = qtern(((float)acc[t][nt][1] - hm1[nt])*hs1[nt] + hb1[nt]);
                    *(char2*)(oa + nt*8) = o;
                }
                if (pb < NROWS){
                    char2 o;
                    o.x = qtern(((float)acc[t][nt][2] - hm0[nt])*hs0[nt] + hb0[nt]);
                    o.y = qtern(((float)acc[t][nt][3] - hm1[nt])*hs1[nt] + hb1[nt]);
                    *(char2*)(ob + nt*8) = o;
                }
            }
        }
    }
}

// ---------------- GEMM via ldmatrix + mma.sync (conv5/fc0/fc1) ----------------
template<int K,int N>
__global__ void __launch_bounds__(256) k_gemm(
    const int8_t* __restrict__ in, const int8_t* __restrict__ wt,
    const float* __restrict__ bs, const float* __restrict__ bm, const float* __restrict__ bb,
    int8_t* __restrict__ out)
{
    constexpr int KC = 256, SK = KC+16;
    extern __shared__ int8_t smem[];
    int8_t* s_a = smem;             // 64*SK
    int8_t* s_b = smem + 64*SK;     // 128*SK

    const int tid  = threadIdx.x;
    const int lane = tid & 31;
    const int warp = tid >> 5;
    const int wm   = warp & 1;
    const int wn   = warp >> 1;
    const int m0   = blockIdx.x * 64;
    const int n0   = blockIdx.y * 128;

    const uint32_t a32 = (uint32_t)__cvta_generic_to_shared(s_a);
    const uint32_t b32 = (uint32_t)__cvta_generic_to_shared(s_b);
    const int laneR = lane & 15;
    const int laneC = (lane >> 4) * 16;

    int acc[2][4][4];
    #pragma unroll
    for (int t=0;t<2;t++)
        #pragma unroll
        for (int nt=0;nt<4;nt++){ acc[t][nt][0]=acc[t][nt][1]=acc[t][nt][2]=acc[t][nt][3]=0; }

    for (int kc = 0; kc < K; kc += KC){
        if (kc) __syncthreads();
        for (int i = tid; i < 64*16; i += 256){
            int row = i >> 4, j = i & 15;
            ((int4*)s_a)[row*17 + j] = *(const int4*)(in + (size_t)(m0+row)*K + kc + j*16);
        }
        for (int i = tid; i < 128*16; i += 256){
            int row = i >> 4, j = i & 15;
            ((int4*)s_b)[row*17 + j] = *(const int4*)(wt + (size_t)(n0+row)*K + kc + j*16);
        }
        __syncthreads();

        #pragma unroll
        for (int ch = 0; ch < KC/32; ch++){
            int a0,a1,a2,a3,a4,a5,a6,a7;
            ldsm_x4(a32 + (wm*32 + laneR)*SK + laneC + ch*32,      a0,a1,a2,a3);
            ldsm_x4(a32 + (wm*32 + 16 + laneR)*SK + laneC + ch*32, a4,a5,a6,a7);
            int b[4][2];
            #pragma unroll
            for (int p=0; p<2; p++)
                ldsm_x4(b32 + (wn*32 + p*16 + ((lane>>4)<<3) + (lane&7))*SK
                            + ((lane>>3)&1)*16 + ch*32,
                        b[2*p][0], b[2*p][1], b[2*p+1][0], b[2*p+1][1]);
            #pragma unroll
            for (int nt=0; nt<4; nt++){
                mma_s8(acc[0][nt], a0,a1,a2,a3, b[nt][0], b[nt][1]);
                mma_s8(acc[1][nt], a4,a5,a6,a7, b[nt][0], b[nt][1]);
            }
        }
    }

    #pragma unroll
    for (int nt=0; nt<4; nt++){
        const int col = n0 + wn*32 + nt*8 + (lane&3)*2;
        const float s0 = bs[col],   m_ = bm[col],   b0_ = bb[col];
        const float s1 = bs[col+1], m1 = bm[col+1], b1_ = bb[col+1];
        #pragma unroll
        for (int t=0; t<2; t++){
            const int ra = m0 + wm*32 + 16*t + (lane>>2);
            char2 o;
            o.x = qtern(((float)acc[t][nt][0] - m_)*s0 + b0_);
            o.y = qtern(((float)acc[t][nt][1] - m1)*s1 + b1_);
            *(char2*)(out + (size_t)ra*N + col) = o;
            o.x = qtern(((float)acc[t][nt][2] - m_)*s0 + b0_);
            o.y = qtern(((float)acc[t][nt][3] - m1)*s1 + b1_);
            *(char2*)(out + (size_t)(ra+8)*N + col) = o;
        }
    }
}

// ---------------- pool ----------------
template<int C,int HIN,int WIN>
__global__ void k_pool(const int8_t* __restrict__ in, int8_t* __restrict__ out){
    constexpr int HO=HIN/2, WO=WIN/2, C4=C/4;
    constexpr int TOT = BSZ*HO*WO*C4;
    int idx = blockIdx.x*256 + threadIdx.x;
    if (idx >= TOT) return;
    int c4 = idx % C4;
    int rr = idx / C4;
    int ox = rr % WO; rr /= WO;
    int oy = rr % HO;
    int b  = rr / HO;
    const int8_t* base = in + ((size_t)(b*HIN + 2*oy)*WIN + 2*ox)*C + c4*4;
    char4 a0 = *(const char4*)base;
    char4 a1 = *(const char4*)(base + C);
    char4 a2 = *(const char4*)(base + (size_t)WIN*C);
    char4 a3 = *(const char4*)(base + (size_t)WIN*C + C);
    char4 o;
    o.x = qtern((float)(a0.x+a1.x+a2.x+a3.x) * 0.25f);
    o.y = qtern((float)(a0.y+a1.y+a2.y+a3.y) * 0.25f);
    o.z = qtern((float)(a0.z+a1.z+a2.z+a3.z) * 0.25f);
    o.w = qtern((float)(a0.w+a1.w+a2.w+a3.w) * 0.25f);
    ((char4*)out)[idx] = o;
}

// ---------------- last FC + TensorNorm ----------------
__global__ void k_fc_last(const int8_t* __restrict__ in, const int8_t* __restrict__ wt,
                          const float* __restrict__ tn, float* __restrict__ out){
    __shared__ int8_t s_a[512];
    int b = blockIdx.x, tid = threadIdx.x;
    for (int i = tid; i < 32; i += 256)
        ((int4*)s_a)[i] = ((const int4*)(in + (size_t)b*512))[i];
    __syncthreads();
    if (tid < 10){
        const int4* wr = (const int4*)(wt + (size_t)tid*512);
        int acc = 0;
        #pragma unroll 8
        for (int c=0;c<32;c++){
            int4 a = ((const int4*)s_a)[c];
            int4 w = wr[c];
            acc=__dp4a(a.x,w.x,acc); acc=__dp4a(a.y,w.y,acc);
            acc=__dp4a(a.z,w.z,acc); acc=__dp4a(a.w,w.w,acc);
        }
        float y = ((float)acc - tn[2]) / sqrtf(tn[3] + 1e-4f) * tn[0] + tn[1];
        out[b*10 + tid] = y;
    }
}

// ---------------- host ----------------
extern "C" void kernel_launch(void* const* d_in, const int* in_sizes, int n_in,
                              void* d_out, int out_size)
{
    const float *x=0, *wc[6]={0,0,0,0,0,0}, *bnc[6]={0,0,0,0,0,0};
    const float *wf[3]={0,0,0}, *bnf[2]={0,0}, *tn=0;
    int n256=0, n512=0, n1024=0, n2048=0;
    for (int i=0;i<n_in;i++){
        const float* p = (const float*)d_in[i];
        switch (in_sizes[i]){
            case 3145728: x = p; break;
            case 1728:    wc[0]=p; break;
            case 36864:   wc[1]=p; break;
            case 73728:   wc[2]=p; break;
            case 147456:  wc[3]=p; break;
            case 294912:  wc[4]=p; break;
            case 589824:  wc[5]=p; break;
            case 131072:  wf[0]=p; break;
            case 262144:  wf[1]=p; break;
            case 5120:    wf[2]=p; break;
            case 256:     if(n256 <2) bnc[0+n256++ ]=p; break;
            case 512:     if(n512 <2) bnc[2+n512++ ]=p; break;
            case 1024:    if(n1024<2) bnc[4+n1024++]=p; break;
            case 2048:    if(n2048<2) bnf[n2048++  ]=p; break;
            case 4:       tn = p; break;
            default: break;
        }
    }

    int8_t *c0,*c1,*p1,*c2,*c3,*p3,*c4,*c5,*f0,*f1;
    int8_t *w0,*w1,*w2,*w3,*w4,*w5,*wf0d,*wf1d,*wf2d;
    float *bns,*bnm,*bnb,*fns,*fnm,*fnb;
    cudaGetSymbolAddress((void**)&c0, g_c0);
    cudaGetSymbolAddress((void**)&c1, g_c1);  cudaGetSymbolAddress((void**)&p1, g_p1);
    cudaGetSymbolAddress((void**)&c2, g_c2);  cudaGetSymbolAddress((void**)&c3, g_c3);
    cudaGetSymbolAddress((void**)&p3, g_p3);  cudaGetSymbolAddress((void**)&c4, g_c4);
    cudaGetSymbolAddress((void**)&c5, g_c5);  cudaGetSymbolAddress((void**)&f0, g_f0);
    cudaGetSymbolAddress((void**)&f1, g_f1);
    cudaGetSymbolAddress((void**)&w0, g_w0);  cudaGetSymbolAddress((void**)&w1, g_w1);
    cudaGetSymbolAddress((void**)&w2, g_w2);  cudaGetSymbolAddress((void**)&w3, g_w3);
    cudaGetSymbolAddress((void**)&w4, g_w4);  cudaGetSymbolAddress((void**)&w5, g_w5);
    cudaGetSymbolAddress((void**)&wf0d, g_wf0); cudaGetSymbolAddress((void**)&wf1d, g_wf1);
    cudaGetSymbolAddress((void**)&wf2d, g_wf2);
    cudaGetSymbolAddress((void**)&bns, g_bns); cudaGetSymbolAddress((void**)&bnm, g_bnm);
    cudaGetSymbolAddress((void**)&bnb, g_bnb);
    cudaGetSymbolAddress((void**)&fns, g_fns); cudaGetSymbolAddress((void**)&fnm, g_fnm);
    cudaGetSymbolAddress((void**)&fnb, g_fnb);

    const int T = 256;
    const int GSM = 64*272 + 128*272;            // 52,224 gemm smem

    // launch 0: all weights
    k_wprep_all<<<(1543424+T-1)/T, T>>>(wc[0],wc[1],wc[2],wc[3],wc[4],wc[5],
                                        wf[0],wf[1],wf[2]);
    // launch 1: all bn
    k_bnprep_all<<<8, 512>>>(bnc[0],bnc[1],bnc[2],bnc[3],bnc[4],bnc[5], bnf[0],bnf[1]);
    // launch 2: conv0 (fused inquant)
    k_conv0<<<1024, T>>>(x, w0, bns, bnm, bnb, c0);
    // launch 3: conv1 (NIMG=1, OCT=64)
    {
        const int SM = 1*900*80 + 64*592;        // 109,888
        cudaFuncSetAttribute(k_cmma<64,64,64,30,30,1>,
                             cudaFuncAttributeMaxDynamicSharedMemorySize, SM);
        k_cmma<64,64,64,30,30,1><<<dim3(1024,1), T, SM>>>(c0, w1, bns+256, bnm+256, bnb+256, c1);
    }
    // launch 4: pool1
    k_pool<64,28,28><<<(BSZ*14*14*16+T-1)/T, T>>>(c1, p1);
    // launch 5: conv2 (NIMG=4, OCT=64)
    {
        const int SM = 4*196*80 + 64*592;        // 100,608
        cudaFuncSetAttribute(k_cmma<64,128,64,14,14,4>,
                             cudaFuncAttributeMaxDynamicSharedMemorySize, SM);
        k_cmma<64,128,64,14,14,4><<<dim3(256,2), T, SM>>>(p1, w2, bns+512, bnm+512, bnb+512, c2);
    }
    // launch 6: conv3 (NIMG=4, OCT=64)
    {
        const int SM = 4*144*144 + 64*1168;      // 157,696
        cudaFuncSetAttribute(k_cmma<128,128,64,12,12,4>,
                             cudaFuncAttributeMaxDynamicSharedMemorySize, SM);
        k_cmma<128,128,64,12,12,4><<<dim3(256,2), T, SM>>>(c2, w3, bns+768, bnm+768, bnb+768, c3);
    }
    // launch 7: pool3
    k_pool<128,10,10><<<(BSZ*5*5*32+T-1)/T, T>>>(c3, p3);
    // launch 8: conv4 (NIMG=8, OCT=64)
    {
        const int SM = 8*25*144 + 64*1168;       // 103,552
        cudaFuncSetAttribute(k_cmma<128,256,64,5,5,8>,
                             cudaFuncAttributeMaxDynamicSharedMemorySize, SM);
        k_cmma<128,256,64,5,5,8><<<dim3(128,4), T, SM>>>(p3, w4, bns+1024, bnm+1024, bnb+1024, c4);
    }
    // launch 9: conv5 as GEMM (M=1024, N=256, K=2304)
    cudaFuncSetAttribute(k_gemm<2304,256>, cudaFuncAttributeMaxDynamicSharedMemorySize, GSM);
    k_gemm<2304,256><<<dim3(16,2), T, GSM>>>(c4, w5, bns+1280, bnm+1280, bnb+1280, c5);
    // launch 10: fc0 (K=256, N=512)
    cudaFuncSetAttribute(k_gemm<256,512>, cudaFuncAttributeMaxDynamicSharedMemorySize, GSM);
    k_gemm<256,512><<<dim3(16,4), T, GSM>>>(c5, wf0d, fns, fnm, fnb, f0);
    // launch 11: fc1 (K=512, N=512)
    cudaFuncSetAttribute(k_gemm<512,512>, cudaFuncAttributeMaxDynamicSharedMemorySize, GSM);
    k_gemm<512,512><<<dim3(16,4), T, GSM>>>(f0, wf1d, fns+512, fnm+512, fnb+512, f1);
    // launch 12: fc2 + TensorNorm
    k_fc_last<<<BSZ, T>>>(f1, wf2d, tn, (float*)d_out);
}